// round 3
// baseline (speedup 1.0000x reference)
#include <cuda_runtime.h>
#include <cuda_bf16.h>
#include <cstdint>

#define DEVI __device__ __forceinline__
typedef __nv_bfloat16 bf16;

constexpr int B_ = 2, S_ = 2048, H_ = 1024, N_ = 16, D_ = 64;
constexpr int MROWS = B_ * S_;            // 4096
constexpr int QKVN = 3 * N_ * D_;         // 3072
constexpr long PLANE = (long)S_ * D_;     // 131072
constexpr long MPLANE = (long)B_ * N_ * PLANE; // q/k/v plane stride
constexpr float L2E = 1.4426950408889634f;

// ------------- static scratch (no allocation) -------------
__device__ __align__(16) bf16 g_xh[MROWS * H_];
__device__ __align__(16) bf16 g_xl[MROWS * H_];
__device__ __align__(16) bf16 g_wh[H_ * QKVN];
__device__ __align__(16) bf16 g_wl[H_ * QKVN];
__device__ __align__(16) bf16 g_owh[H_ * H_];
__device__ __align__(16) bf16 g_owl[H_ * H_];
__device__ __align__(16) bf16 g_qkvh[3 * B_ * N_ * S_ * D_];
__device__ __align__(16) bf16 g_qkvl[3 * B_ * N_ * S_ * D_];
__device__ __align__(16) bf16 g_mixh[B_ * N_ * S_ * D_];
__device__ __align__(16) bf16 g_mixl[B_ * N_ * S_ * D_];
__device__ float g_cum[N_ * S_];

// ------------- helpers -------------
DEVI uint32_t sma(const void* p) { return (uint32_t)__cvta_generic_to_shared(p); }

DEVI void ldsm4(uint32_t r[4], uint32_t a) {
  asm volatile("ldmatrix.sync.aligned.m8n8.x4.shared.b16 {%0,%1,%2,%3},[%4];\n"
               : "=r"(r[0]), "=r"(r[1]), "=r"(r[2]), "=r"(r[3]) : "r"(a));
}
DEVI void ldsm4t(uint32_t r[4], uint32_t a) {
  asm volatile("ldmatrix.sync.aligned.m8n8.x4.trans.shared.b16 {%0,%1,%2,%3},[%4];\n"
               : "=r"(r[0]), "=r"(r[1]), "=r"(r[2]), "=r"(r[3]) : "r"(a));
}
DEVI void mma16816(float c[4], const uint32_t a[4], uint32_t b0, uint32_t b1) {
  asm volatile(
      "mma.sync.aligned.m16n8k16.row.col.f32.bf16.bf16.f32 "
      "{%0,%1,%2,%3},{%4,%5,%6,%7},{%8,%9},{%0,%1,%2,%3};\n"
      : "+f"(c[0]), "+f"(c[1]), "+f"(c[2]), "+f"(c[3])
      : "r"(a[0]), "r"(a[1]), "r"(a[2]), "r"(a[3]), "r"(b0), "r"(b1));
}
DEVI float e2(float x) { float r; asm("ex2.approx.f32 %0,%1;" : "=f"(r) : "f"(x)); return r; }
DEVI float bres(float x) { return x - __bfloat162float(__float2bfloat16_rn(x)); }
DEVI uint32_t pack2(float lo, float hi) {
  return (uint32_t)__bfloat16_as_ushort(__float2bfloat16_rn(lo)) |
         ((uint32_t)__bfloat16_as_ushort(__float2bfloat16_rn(hi)) << 16);
}

// ------------- split fp32 -> bf16 hi/lo -------------
__global__ void split_kernel(const float* __restrict__ src, int n, int sel) {
  int i = blockIdx.x * blockDim.x + threadIdx.x;
  if (i >= n) return;
  bf16* h = sel == 0 ? g_xh : (sel == 1 ? g_wh : g_owh);
  bf16* l = sel == 0 ? g_xl : (sel == 1 ? g_wl : g_owl);
  float v = src[i];
  bf16 hi = __float2bfloat16_rn(v);
  h[i] = hi;
  l[i] = __float2bfloat16_rn(v - __bfloat162float(hi));
}

// ------------- cumsum rows of rpe_bias -------------
__global__ void cumsum_kernel(const float* __restrict__ rpe) {
  int w = threadIdx.x >> 5, lane = threadIdx.x & 31;
  if (w >= N_) return;
  float carry = 0.f;
  for (int c = 0; c < S_ / 32; c++) {
    float v = rpe[w * S_ + c * 32 + lane];
#pragma unroll
    for (int o = 1; o < 32; o <<= 1) {
      float t = __shfl_up_sync(0xffffffffu, v, o);
      if (lane >= o) v += t;
    }
    v += carry;
    g_cum[w * S_ + c * 32 + lane] = v;
    carry = __shfl_sync(0xffffffffu, v, 31);
  }
}

// ------------- split-bf16 GEMM (Ah*Bh + Ah*Bl + Al*Bh) -------------
// MODE 0: x[4096,1024] @ w[1024,3072] -> q/k/v hi/lo planes (q scaled 1/8)
// MODE 1: mix(planes)[4096,1024] @ ow[1024,1024] -> fp32 d_out
template <int MODE>
__global__ __launch_bounds__(256) void gemm_kernel(float* __restrict__ outp) {
  constexpr int Nn = (MODE == 0) ? QKVN : H_;
  const bf16* __restrict__ Ah = (MODE == 0) ? g_xh : g_mixh;
  const bf16* __restrict__ Al = (MODE == 0) ? g_xl : g_mixl;
  const bf16* __restrict__ Bh = (MODE == 0) ? g_wh : g_owh;
  const bf16* __restrict__ Bl = (MODE == 0) ? g_wl : g_owl;

  __shared__ __align__(16) bf16 sA[2][128 * 40];
  __shared__ __align__(16) bf16 sB[2][32 * 72];

  const int tid = threadIdx.x, w = tid >> 5, lane = tid & 31;
  const int wm = w & 3, wn = w >> 2;
  const int row0 = blockIdx.y * 128, col0 = blockIdx.x * 64;

  float acc[2][4][4];
#pragma unroll
  for (int a = 0; a < 2; a++)
#pragma unroll
    for (int b = 0; b < 4; b++)
#pragma unroll
      for (int c = 0; c < 4; c++) acc[a][b][c] = 0.f;

  for (int kt = 0; kt < H_; kt += 32) {
    __syncthreads();
#pragma unroll
    for (int p = 0; p < 2; p++) {  // A tile 128x32
      int i = tid + 256 * p;
      int r = i >> 2, seg = i & 3;
      int rg = row0 + r;
      long off;
      if (MODE == 0) {
        off = (long)rg * H_ + kt + seg * 8;
      } else {
        int k = kt + seg * 8;
        off = ((long)((rg >> 11) * N_ + (k >> 6)) * S_ + (rg & 2047)) * D_ + (k & 63);
      }
      *(uint4*)&sA[0][r * 40 + seg * 8] = *(const uint4*)&Ah[off];
      *(uint4*)&sA[1][r * 40 + seg * 8] = *(const uint4*)&Al[off];
    }
    {  // B tile 32x64, natural [k][n]
      int r = tid >> 3, c8 = tid & 7;
      long off = (long)(kt + r) * Nn + col0 + c8 * 8;
      *(uint4*)&sB[0][r * 72 + c8 * 8] = *(const uint4*)&Bh[off];
      *(uint4*)&sB[1][r * 72 + c8 * 8] = *(const uint4*)&Bl[off];
    }
    __syncthreads();
#pragma unroll
    for (int kc = 0; kc < 2; kc++) {
      uint32_t afh[2][4], afl[2][4];
#pragma unroll
      for (int mi = 0; mi < 2; mi++) {
        int r = wm * 32 + mi * 16 + (lane & 15);
        int cc = kc * 16 + (lane >> 4) * 8;
        ldsm4(afh[mi], sma(&sA[0][r * 40 + cc]));
        ldsm4(afl[mi], sma(&sA[1][r * 40 + cc]));
      }
#pragma unroll
      for (int pr = 0; pr < 2; pr++) {
        uint32_t bh4[4], bl4[4];
        int g = lane >> 3, r = lane & 7;
        int rb = kc * 16 + r + ((g & 1) ? 8 : 0);
        int cb = wn * 32 + pr * 16 + ((g >= 2) ? 8 : 0);
        ldsm4t(bh4, sma(&sB[0][rb * 72 + cb]));
        ldsm4t(bl4, sma(&sB[1][rb * 72 + cb]));
#pragma unroll
        for (int mi = 0; mi < 2; mi++) {
          mma16816(acc[mi][2 * pr], afh[mi], bh4[0], bh4[1]);
          mma16816(acc[mi][2 * pr], afh[mi], bl4[0], bl4[1]);
          mma16816(acc[mi][2 * pr], afl[mi], bh4[0], bh4[1]);
          mma16816(acc[mi][2 * pr + 1], afh[mi], bh4[2], bh4[3]);
          mma16816(acc[mi][2 * pr + 1], afh[mi], bl4[2], bl4[3]);
          mma16816(acc[mi][2 * pr + 1], afl[mi], bh4[2], bh4[3]);
        }
      }
    }
  }
  // epilogue
#pragma unroll
  for (int mi = 0; mi < 2; mi++)
#pragma unroll
    for (int nj = 0; nj < 4; nj++)
#pragma unroll
      for (int v = 0; v < 4; v++) {
        int rg = row0 + wm * 32 + mi * 16 + (lane >> 2) + ((v & 2) ? 8 : 0);
        int c = col0 + wn * 32 + nj * 8 + 2 * (lane & 3) + (v & 1);
        float val = acc[mi][nj][v];
        if (MODE == 0) {
          int m = c >> 10, nh = (c >> 6) & 15, d = c & 63;
          if (m == 0) val *= 0.125f;  // D^-0.5
          int b = rg >> 11, s = rg & 2047;
          long idx = ((long)(m * 32 + b * 16 + nh)) * PLANE + (long)s * D_ + d;
          bf16 hi = __float2bfloat16_rn(val);
          g_qkvh[idx] = hi;
          g_qkvl[idx] = __float2bfloat16_rn(val - __bfloat162float(hi));
        } else {
          outp[(long)rg * H_ + c] = val;
        }
      }
}

// ------------- causal flash attention with cum-bias -------------
__global__ __launch_bounds__(256) void flash_kernel() {
  const int qt = 15 - blockIdx.x;  // heavy tiles first
  const int bh = blockIdx.y;       // b*16+n
  const int n = bh & 15;
  const int q0 = qt * 128;
  const int tid = threadIdx.x, w = tid >> 5, lane = tid & 31;

  __shared__ __align__(16) bf16 sm[4 * 64 * 72];
  bf16* sQh = sm;               // [128][72] (phase 1)
  bf16* sQl = sm + 128 * 72;
  bf16* sKh = sm;               // [64][72] (phase 2, reuse)
  bf16* sKl = sm + 64 * 72;
  bf16* sVh = sm + 2 * 64 * 72;
  bf16* sVl = sm + 3 * 64 * 72;

  const long pl = (long)bh * PLANE;
  const bf16 *qh_g = g_qkvh + pl, *ql_g = g_qkvl + pl;
  const bf16 *kh_g = g_qkvh + MPLANE + pl, *kl_g = g_qkvl + MPLANE + pl;
  const bf16 *vh_g = g_qkvh + 2 * MPLANE + pl, *vl_g = g_qkvl + 2 * MPLANE + pl;

#pragma unroll
  for (int p = 0; p < 4; p++) {  // Q tile 128x64
    int i = tid + 256 * p;
    int r = i >> 3, c8 = i & 7;
    long g = (long)(q0 + r) * D_ + c8 * 8;
    *(uint4*)&sQh[r * 72 + c8 * 8] = *(const uint4*)&qh_g[g];
    *(uint4*)&sQl[r * 72 + c8 * 8] = *(const uint4*)&ql_g[g];
  }
  __syncthreads();
  uint32_t qfh[4][4], qfl[4][4];
  {
    int r = w * 16 + (lane & 15), cb = (lane >> 4) * 8;
#pragma unroll
    for (int kc = 0; kc < 4; kc++) {
      ldsm4(qfh[kc], sma(&sQh[r * 72 + kc * 16 + cb]));
      ldsm4(qfl[kc], sma(&sQl[r * 72 + kc * 16 + cb]));
    }
  }
  __syncthreads();

  float Oa[8][4];
#pragma unroll
  for (int j = 0; j < 8; j++)
#pragma unroll
    for (int v = 0; v < 4; v++) Oa[j][v] = 0.f;
  float mrow[2] = {-1e30f, -1e30f}, lrow[2] = {0.f, 0.f};
  const float* cumn = g_cum + n * S_;
  const int ntiles = 2 * qt + 2;
  const int itop = q0 + w * 16 + 15;

  for (int t = 0; t < ntiles; t++) {
    const int kv0 = t * 64;
#pragma unroll
    for (int p = 0; p < 2; p++) {  // K,V tiles 64x64 (hi+lo)
      int i = tid + 256 * p;
      int r = i >> 3, c8 = i & 7;
      long g = (long)(kv0 + r) * D_ + c8 * 8;
      *(uint4*)&sKh[r * 72 + c8 * 8] = *(const uint4*)&kh_g[g];
      *(uint4*)&sKl[r * 72 + c8 * 8] = *(const uint4*)&kl_g[g];
      *(uint4*)&sVh[r * 72 + c8 * 8] = *(const uint4*)&vh_g[g];
      *(uint4*)&sVl[r * 72 + c8 * 8] = *(const uint4*)&vl_g[g];
    }
    __syncthreads();
    if (kv0 <= itop) {
      float sc[8][4];
#pragma unroll
      for (int j = 0; j < 8; j++)
#pragma unroll
        for (int v = 0; v < 4; v++) sc[j][v] = 0.f;
      // S = Q K^T (split, 3 products)
#pragma unroll
      for (int kc = 0; kc < 4; kc++) {
#pragma unroll
        for (int pr = 0; pr < 4; pr++) {
          uint32_t bh4[4], bl4[4];
          int g = lane >> 3, r = lane & 7;
          int rk = pr * 16 + r + ((g >= 2) ? 8 : 0);
          int ck = kc * 16 + ((g & 1) ? 8 : 0);
          ldsm4(bh4, sma(&sKh[rk * 72 + ck]));
          ldsm4(bl4, sma(&sKl[rk * 72 + ck]));
          mma16816(sc[2 * pr], qfh[kc], bh4[0], bh4[1]);
          mma16816(sc[2 * pr], qfh[kc], bl4[0], bl4[1]);
          mma16816(sc[2 * pr], qfl[kc], bh4[0], bh4[1]);
          mma16816(sc[2 * pr + 1], qfh[kc], bh4[2], bh4[3]);
          mma16816(sc[2 * pr + 1], qfh[kc], bl4[2], bl4[3]);
          mma16816(sc[2 * pr + 1], qfl[kc], bh4[2], bh4[3]);
        }
      }
      // bias + mask + online softmax
      const int rb = q0 + w * 16 + (lane >> 2);
      const int cb = kv0 + 2 * (lane & 3);
      float mx[2] = {-1e30f, -1e30f};
#pragma unroll
      for (int j = 0; j < 8; j++)
#pragma unroll
        for (int v = 0; v < 4; v++) {
          int ii = rb + ((v & 2) ? 8 : 0);
          int jj = cb + j * 8 + (v & 1);
          int dlt = ii - jj;
          float s = (dlt < 0) ? -1e30f : sc[j][v] + __ldg(&cumn[dlt]);
          sc[j][v] = s;
          mx[v >> 1] = fmaxf(mx[v >> 1], s);
        }
#pragma unroll
      for (int h = 0; h < 2; h++) {
        mx[h] = fmaxf(mx[h], __shfl_xor_sync(0xffffffffu, mx[h], 1));
        mx[h] = fmaxf(mx[h], __shfl_xor_sync(0xffffffffu, mx[h], 2));
      }
      float al[2], sum[2] = {0.f, 0.f};
#pragma unroll
      for (int h = 0; h < 2; h++) {
        float mn = fmaxf(mrow[h], mx[h]);
        al[h] = e2((mrow[h] - mn) * L2E);
        mrow[h] = mn;
      }
#pragma unroll
      for (int j = 0; j < 8; j++)
#pragma unroll
        for (int v = 0; v < 4; v++) {
          float p = e2((sc[j][v] - mrow[v >> 1]) * L2E);
          sc[j][v] = p;
          sum[v >> 1] += p;
        }
#pragma unroll
      for (int h = 0; h < 2; h++) {
        sum[h] += __shfl_xor_sync(0xffffffffu, sum[h], 1);
        sum[h] += __shfl_xor_sync(0xffffffffu, sum[h], 2);
        lrow[h] = lrow[h] * al[h] + sum[h];
      }
#pragma unroll
      for (int j = 0; j < 8; j++)
#pragma unroll
        for (int v = 0; v < 4; v++) Oa[j][v] *= al[v >> 1];
      // O += P V (split P, split V, 3 products)
#pragma unroll
      for (int kc = 0; kc < 4; kc++) {
        uint32_t ah[4], alo[4];
        ah[0] = pack2(sc[2 * kc][0], sc[2 * kc][1]);
        ah[1] = pack2(sc[2 * kc][2], sc[2 * kc][3]);
        ah[2] = pack2(sc[2 * kc + 1][0], sc[2 * kc + 1][1]);
        ah[3] = pack2(sc[2 * kc + 1][2], sc[2 * kc + 1][3]);
        alo[0] = pack2(bres(sc[2 * kc][0]), bres(sc[2 * kc][1]));
        alo[1] = pack2(bres(sc[2 * kc][2]), bres(sc[2 * kc][3]));
        alo[2] = pack2(bres(sc[2 * kc + 1][0]), bres(sc[2 * kc + 1][1]));
        alo[3] = pack2(bres(sc[2 * kc + 1][2]), bres(sc[2 * kc + 1][3]));
#pragma unroll
        for (int pr = 0; pr < 4; pr++) {
          uint32_t bh4[4], bl4[4];
          int g = lane >> 3, r = lane & 7;
          int rv = kc * 16 + r + ((g & 1) ? 8 : 0);
          int cv = pr * 16 + ((g >= 2) ? 8 : 0);
          ldsm4t(bh4, sma(&sVh[rv * 72 + cv]));
          ldsm4t(bl4, sma(&sVl[rv * 72 + cv]));
          mma16816(Oa[2 * pr], ah, bh4[0], bh4[1]);
          mma16816(Oa[2 * pr], ah, bl4[0], bl4[1]);
          mma16816(Oa[2 * pr], alo, bh4[0], bh4[1]);
          mma16816(Oa[2 * pr + 1], ah, bh4[2], bh4[3]);
          mma16816(Oa[2 * pr + 1], ah, bl4[2], bl4[3]);
          mma16816(Oa[2 * pr + 1], alo, bh4[2], bh4[3]);
        }
      }
    }
    __syncthreads();
  }
  // epilogue -> mix hi/lo planes
  float inv[2] = {1.f / lrow[0], 1.f / lrow[1]};
  bf16* mh = g_mixh + pl;
  bf16* ml = g_mixl + pl;
#pragma unroll
  for (int j = 0; j < 8; j++)
#pragma unroll
    for (int v = 0; v < 4; v++) {
      int ii = q0 + w * 16 + (lane >> 2) + ((v & 2) ? 8 : 0);
      int d = j * 8 + 2 * (lane & 3) + (v & 1);
      float val = Oa[j][v] * inv[v >> 1];
      bf16 hi = __float2bfloat16_rn(val);
      mh[(long)ii * D_ + d] = hi;
      ml[(long)ii * D_ + d] = __float2bfloat16_rn(val - __bfloat162float(hi));
    }
}

// ------------- launch -------------
extern "C" void kernel_launch(void* const* d_in, const int* in_sizes, int n_in,
                              void* d_out, int out_size) {
  const float* x = (const float*)d_in[0];
  const float* qkv = (const float*)d_in[1];
  const float* ow = (const float*)d_in[2];
  const float* rpe = (const float*)d_in[3];
  float* out = (float*)d_out;

  split_kernel<<<(MROWS * H_ + 255) / 256, 256>>>(x, MROWS * H_, 0);
  split_kernel<<<(H_ * QKVN + 255) / 256, 256>>>(qkv, H_ * QKVN, 1);
  split_kernel<<<(H_ * H_ + 255) / 256, 256>>>(ow, H_ * H_, 2);
  cumsum_kernel<<<1, 512>>>(rpe);
  gemm_kernel<0><<<dim3(QKVN / 64, MROWS / 128), 256>>>(nullptr);
  flash_kernel<<<dim3(16, B_ * N_), 256>>>();
  gemm_kernel<1><<<dim3(H_ / 64, MROWS / 128), 256>>>(out);
}

// round 4
// speedup vs baseline: 1.2317x; 1.2317x over previous
#include <cuda_runtime.h>
#include <cuda_bf16.h>
#include <cuda_fp16.h>
#include <cstdint>

#define DEVI __device__ __forceinline__
typedef __nv_bfloat16 bf16;

constexpr int B_ = 2, S_ = 2048, H_ = 1024, N_ = 16, D_ = 64;
constexpr int MROWS = B_ * S_;             // 4096
constexpr int QKVN = 3 * N_ * D_;          // 3072
constexpr long PLANE = (long)S_ * D_;      // 131072
constexpr long MPLANE = (long)B_ * N_ * PLANE;
constexpr float L2E = 1.4426950408889634f;

// ------------- static scratch -------------
__device__ __align__(16) bf16 g_xh[MROWS * H_];
__device__ __align__(16) bf16 g_xl[MROWS * H_];
__device__ __align__(16) bf16 g_wh[H_ * QKVN];
__device__ __align__(16) bf16 g_wl[H_ * QKVN];
__device__ __align__(16) bf16 g_owh[H_ * H_];
__device__ __align__(16) bf16 g_owl[H_ * H_];
__device__ __align__(16) __half g_qkvf[3 * B_ * N_ * S_ * D_];  // fp16 q/k/v
__device__ __align__(16) bf16 g_mixh[B_ * N_ * S_ * D_];
__device__ __align__(16) bf16 g_mixl[B_ * N_ * S_ * D_];
__device__ float g_cum[N_ * S_];

// ------------- helpers -------------
DEVI uint32_t sma(const void* p) { return (uint32_t)__cvta_generic_to_shared(p); }
DEVI void ldsm4(uint32_t r[4], uint32_t a) {
  asm volatile("ldmatrix.sync.aligned.m8n8.x4.shared.b16 {%0,%1,%2,%3},[%4];\n"
               : "=r"(r[0]), "=r"(r[1]), "=r"(r[2]), "=r"(r[3]) : "r"(a));
}
DEVI void ldsm4t(uint32_t r[4], uint32_t a) {
  asm volatile("ldmatrix.sync.aligned.m8n8.x4.trans.shared.b16 {%0,%1,%2,%3},[%4];\n"
               : "=r"(r[0]), "=r"(r[1]), "=r"(r[2]), "=r"(r[3]) : "r"(a));
}
DEVI void mma_bf(float c[4], const uint32_t a[4], uint32_t b0, uint32_t b1) {
  asm volatile(
      "mma.sync.aligned.m16n8k16.row.col.f32.bf16.bf16.f32 "
      "{%0,%1,%2,%3},{%4,%5,%6,%7},{%8,%9},{%0,%1,%2,%3};\n"
      : "+f"(c[0]), "+f"(c[1]), "+f"(c[2]), "+f"(c[3])
      : "r"(a[0]), "r"(a[1]), "r"(a[2]), "r"(a[3]), "r"(b0), "r"(b1));
}
DEVI void mma_h(float c[4], const uint32_t a[4], uint32_t b0, uint32_t b1) {
  asm volatile(
      "mma.sync.aligned.m16n8k16.row.col.f32.f16.f16.f32 "
      "{%0,%1,%2,%3},{%4,%5,%6,%7},{%8,%9},{%0,%1,%2,%3};\n"
      : "+f"(c[0]), "+f"(c[1]), "+f"(c[2]), "+f"(c[3])
      : "r"(a[0]), "r"(a[1]), "r"(a[2]), "r"(a[3]), "r"(b0), "r"(b1));
}
DEVI float e2(float x) { float r; asm("ex2.approx.f32 %0,%1;" : "=f"(r) : "f"(x)); return r; }
DEVI uint32_t pack2h(float lo, float hi) {
  __half2 h = __floats2half2_rn(lo, hi);
  uint32_t u; memcpy(&u, &h, 4); return u;
}
DEVI void cpa(uint32_t dst, const void* src) {
  asm volatile("cp.async.cg.shared.global [%0], [%1], 16;\n" :: "r"(dst), "l"(src));
}
DEVI void cpcommit() { asm volatile("cp.async.commit_group;\n"); }
template <int n> DEVI void cpwait() { asm volatile("cp.async.wait_group %0;\n" :: "n"(n)); }

// ------------- split fp32 -> bf16 hi/lo -------------
__global__ void split_kernel(const float* __restrict__ src, int n, int sel) {
  int i = blockIdx.x * blockDim.x + threadIdx.x;
  if (i >= n) return;
  bf16* h = sel == 0 ? g_xh : (sel == 1 ? g_wh : g_owh);
  bf16* l = sel == 0 ? g_xl : (sel == 1 ? g_wl : g_owl);
  float v = src[i];
  bf16 hi = __float2bfloat16_rn(v);
  h[i] = hi;
  l[i] = __float2bfloat16_rn(v - __bfloat162float(hi));
}

// ------------- cumsum: one block per head, two-level scan -------------
__global__ void cumsum_kernel(const float* __restrict__ rpe) {
  int n = blockIdx.x, t = threadIdx.x, lane = t & 31, w = t >> 5;
  __shared__ float ws[8];
  float v[8];
  const float* row = rpe + n * S_;
#pragma unroll
  for (int j = 0; j < 8; j++) v[j] = row[t * 8 + j];
#pragma unroll
  for (int j = 1; j < 8; j++) v[j] += v[j - 1];
  float s = v[7];
#pragma unroll
  for (int o = 1; o < 32; o <<= 1) {
    float x = __shfl_up_sync(0xffffffffu, s, o);
    if (lane >= o) s += x;
  }
  if (lane == 31) ws[w] = s;
  __syncthreads();
  if (w == 0) {
    float x = (lane < 8) ? ws[lane] : 0.f;
#pragma unroll
    for (int o = 1; o < 8; o <<= 1) {
      float y = __shfl_up_sync(0xffffffffu, x, o);
      if (lane >= o) x += y;
    }
    if (lane < 8) ws[lane] = x;
  }
  __syncthreads();
  float off = s - v[7] + (w ? ws[w - 1] : 0.f);
#pragma unroll
  for (int j = 0; j < 8; j++) g_cum[n * S_ + t * 8 + j] = v[j] + off;
}

// ------------- split-bf16 GEMM, cp.async 2-stage, K-step 16 -------------
// MODE 0: x[4096,1024]@w[1024,3072] -> fp16 q/k/v planes (q scaled 1/8)
// MODE 1: mix(planes)@ow[1024,1024] -> fp32 d_out
template <int MODE>
__global__ __launch_bounds__(256) void gemm_kernel(float* __restrict__ outp) {
  constexpr int Nn = (MODE == 0) ? QKVN : H_;
  const bf16* __restrict__ Ah = (MODE == 0) ? g_xh : g_mixh;
  const bf16* __restrict__ Al = (MODE == 0) ? g_xl : g_mixl;
  const bf16* __restrict__ Bh = (MODE == 0) ? g_wh : g_owh;
  const bf16* __restrict__ Bl = (MODE == 0) ? g_wl : g_owl;

  __shared__ __align__(16) bf16 sA[2][2][128 * 24];  // [stage][plane]
  __shared__ __align__(16) bf16 sB[2][2][16 * 72];

  const int tid = threadIdx.x, w = tid >> 5, lane = tid & 31;
  const int wm = w & 3, wn = w >> 2;
  const int row0 = blockIdx.y * 128, col0 = blockIdx.x * 64;

  float acc[2][4][4];
#pragma unroll
  for (int a = 0; a < 2; a++)
#pragma unroll
    for (int b = 0; b < 4; b++)
#pragma unroll
      for (int c = 0; c < 4; c++) acc[a][b][c] = 0.f;

  auto load_tile = [&](int st, int kt) {
    {  // A 128x16, both planes: tid -> r=tid>>1, seg=tid&1
      int r = tid >> 1, seg = tid & 1;
      int rg = row0 + r;
      long off;
      if (MODE == 0) {
        off = (long)rg * H_ + kt + seg * 8;
      } else {
        int k = kt + seg * 8;
        off = ((long)((rg >> 11) * N_ + (k >> 6)) * S_ + (rg & 2047)) * D_ + (k & 63);
      }
      cpa(sma(&sA[st][0][r * 24 + seg * 8]), &Ah[off]);
      cpa(sma(&sA[st][1][r * 24 + seg * 8]), &Al[off]);
    }
    {  // B 16x64, both planes: r=tid>>4 (0..15), c8=tid&15 -> only 8 segs needed
      int r = tid >> 4, c8 = tid & 15;
      if (c8 < 8) {
        long off = (long)(kt + r) * Nn + col0 + c8 * 8;
        cpa(sma(&sB[st][0][r * 72 + c8 * 8]), &Bh[off]);
        cpa(sma(&sB[st][1][r * 72 + c8 * 8]), &Bl[off]);
      }
    }
  };

  load_tile(0, 0);
  cpcommit();
  constexpr int NK = H_ / 16;
  for (int t = 0; t < NK; t++) {
    if (t + 1 < NK) load_tile((t + 1) & 1, (t + 1) * 16);
    cpcommit();
    cpwait<1>();
    __syncthreads();
    const int st = t & 1;
    uint32_t afh[2][4], afl[2][4];
#pragma unroll
    for (int mi = 0; mi < 2; mi++) {
      int r = wm * 32 + mi * 16 + (lane & 15);
      int cc = (lane >> 4) * 8;
      ldsm4(afh[mi], sma(&sA[st][0][r * 24 + cc]));
      ldsm4(afl[mi], sma(&sA[st][1][r * 24 + cc]));
    }
#pragma unroll
    for (int pr = 0; pr < 2; pr++) {
      uint32_t bh4[4], bl4[4];
      int g = lane >> 3, r = lane & 7;
      int rb = r + ((g & 1) ? 8 : 0);
      int cb = wn * 32 + pr * 16 + ((g >= 2) ? 8 : 0);
      ldsm4t(bh4, sma(&sB[st][0][rb * 72 + cb]));
      ldsm4t(bl4, sma(&sB[st][1][rb * 72 + cb]));
#pragma unroll
      for (int mi = 0; mi < 2; mi++) {
        mma_bf(acc[mi][2 * pr], afh[mi], bh4[0], bh4[1]);
        mma_bf(acc[mi][2 * pr], afh[mi], bl4[0], bl4[1]);
        mma_bf(acc[mi][2 * pr], afl[mi], bh4[0], bh4[1]);
        mma_bf(acc[mi][2 * pr + 1], afh[mi], bh4[2], bh4[3]);
        mma_bf(acc[mi][2 * pr + 1], afh[mi], bl4[2], bl4[3]);
        mma_bf(acc[mi][2 * pr + 1], afl[mi], bh4[2], bh4[3]);
      }
    }
    __syncthreads();
  }
  // epilogue
#pragma unroll
  for (int mi = 0; mi < 2; mi++)
#pragma unroll
    for (int nj = 0; nj < 4; nj++)
#pragma unroll
      for (int v = 0; v < 4; v++) {
        int rg = row0 + wm * 32 + mi * 16 + (lane >> 2) + ((v & 2) ? 8 : 0);
        int c = col0 + wn * 32 + nj * 8 + 2 * (lane & 3) + (v & 1);
        float val = acc[mi][nj][v];
        if (MODE == 0) {
          int m = c >> 10, nh = (c >> 6) & 15, d = c & 63;
          if (m == 0) val *= 0.125f;
          int b = rg >> 11, s = rg & 2047;
          long idx = ((long)(m * 32 + b * 16 + nh)) * PLANE + (long)s * D_ + d;
          g_qkvf[idx] = __float2half_rn(val);
        } else {
          outp[(long)rg * H_ + c] = val;
        }
      }
}

// ------------- causal flash attention, fp16, cp.async 2-stage KV -------------
__global__ __launch_bounds__(256) void flash_kernel() {
  const int qt = 15 - blockIdx.x;
  const int bh = blockIdx.y;
  const int n = bh & 15;
  const int q0 = qt * 128;
  const int tid = threadIdx.x, w = tid >> 5, lane = tid & 31;

  __shared__ __align__(16) __half fsm[18432];  // 36 KB: Q overlaps KV ring
  __half* sQ = fsm;  // [128][72], used only in prologue
#define SK(st) (fsm + (st) * 9216)
#define SV(st) (fsm + (st) * 9216 + 4608)

  const long pl = (long)bh * PLANE;
  const __half* qg = g_qkvf + pl;
  const __half* kg = g_qkvf + MPLANE + pl;
  const __half* vg = g_qkvf + 2 * MPLANE + pl;

#pragma unroll
  for (int p = 0; p < 4; p++) {  // Q 128x64
    int i = tid + 256 * p;
    int r = i >> 3, c8 = i & 7;
    *(uint4*)&sQ[r * 72 + c8 * 8] = *(const uint4*)&qg[(long)(q0 + r) * D_ + c8 * 8];
  }
  __syncthreads();
  uint32_t qf[4][4];
  {
    int r = w * 16 + (lane & 15), cb = (lane >> 4) * 8;
#pragma unroll
    for (int kc = 0; kc < 4; kc++) ldsm4(qf[kc], sma(&sQ[r * 72 + kc * 16 + cb]));
  }
  __syncthreads();  // all warps done with Q smem before KV ring overwrites

  float Oa[8][4];
#pragma unroll
  for (int j = 0; j < 8; j++)
#pragma unroll
    for (int v = 0; v < 4; v++) Oa[j][v] = 0.f;
  float mrow[2] = {-1e30f, -1e30f}, lrow[2] = {0.f, 0.f};
  const float* cumn = g_cum + n * S_;
  const int ntiles = 2 * qt + 2;
  const int itop = q0 + w * 16 + 15;

  auto loadkv = [&](int st, int t) {
    int kv0 = t * 64;
#pragma unroll
    for (int p = 0; p < 2; p++) {
      int i = tid + 256 * p;
      int r = i >> 3, c8 = i & 7;
      long g = (long)(kv0 + r) * D_ + c8 * 8;
      cpa(sma(SK(st) + r * 72 + c8 * 8), kg + g);
      cpa(sma(SV(st) + r * 72 + c8 * 8), vg + g);
    }
  };

  loadkv(0, 0);
  cpcommit();
  for (int t = 0; t < ntiles; t++) {
    if (t + 1 < ntiles) loadkv((t + 1) & 1, t + 1);
    cpcommit();
    cpwait<1>();
    __syncthreads();
    const int st = t & 1;
    const int kv0 = t * 64;
    if (kv0 <= itop) {
      float sc[8][4];
#pragma unroll
      for (int j = 0; j < 8; j++)
#pragma unroll
        for (int v = 0; v < 4; v++) sc[j][v] = 0.f;
#pragma unroll
      for (int kc = 0; kc < 4; kc++) {
#pragma unroll
        for (int pr = 0; pr < 4; pr++) {
          uint32_t b4[4];
          int g = lane >> 3, r = lane & 7;
          int rk = pr * 16 + r + ((g >= 2) ? 8 : 0);
          int ck = kc * 16 + ((g & 1) ? 8 : 0);
          ldsm4(b4, sma(SK(st) + rk * 72 + ck));
          mma_h(sc[2 * pr], qf[kc], b4[0], b4[1]);
          mma_h(sc[2 * pr + 1], qf[kc], b4[2], b4[3]);
        }
      }
      // bias + mask + online softmax
      const int rb = q0 + w * 16 + (lane >> 2);
      const int cb = kv0 + 2 * (lane & 3);
      float mx[2] = {-1e30f, -1e30f};
#pragma unroll
      for (int j = 0; j < 8; j++)
#pragma unroll
        for (int v = 0; v < 4; v++) {
          int ii = rb + ((v & 2) ? 8 : 0);
          int jj = cb + j * 8 + (v & 1);
          int dlt = ii - jj;
          float s = (dlt < 0) ? -1e30f : sc[j][v] + __ldg(&cumn[dlt]);
          sc[j][v] = s;
          mx[v >> 1] = fmaxf(mx[v >> 1], s);
        }
#pragma unroll
      for (int h = 0; h < 2; h++) {
        mx[h] = fmaxf(mx[h], __shfl_xor_sync(0xffffffffu, mx[h], 1));
        mx[h] = fmaxf(mx[h], __shfl_xor_sync(0xffffffffu, mx[h], 2));
      }
      float al[2], sum[2] = {0.f, 0.f};
#pragma unroll
      for (int h = 0; h < 2; h++) {
        float mn = fmaxf(mrow[h], mx[h]);
        al[h] = e2((mrow[h] - mn) * L2E);
        mrow[h] = mn;
      }
#pragma unroll
      for (int j = 0; j < 8; j++)
#pragma unroll
        for (int v = 0; v < 4; v++) {
          float p = e2((sc[j][v] - mrow[v >> 1]) * L2E);
          sc[j][v] = p;
          sum[v >> 1] += p;
        }
#pragma unroll
      for (int h = 0; h < 2; h++) {
        sum[h] += __shfl_xor_sync(0xffffffffu, sum[h], 1);
        sum[h] += __shfl_xor_sync(0xffffffffu, sum[h], 2);
        lrow[h] = lrow[h] * al[h] + sum[h];
      }
#pragma unroll
      for (int j = 0; j < 8; j++)
#pragma unroll
        for (int v = 0; v < 4; v++) Oa[j][v] *= al[v >> 1];
      // O += P V
#pragma unroll
      for (int kc = 0; kc < 4; kc++) {
        uint32_t ap[4];
        ap[0] = pack2h(sc[2 * kc][0], sc[2 * kc][1]);
        ap[1] = pack2h(sc[2 * kc][2], sc[2 * kc][3]);
        ap[2] = pack2h(sc[2 * kc + 1][0], sc[2 * kc + 1][1]);
        ap[3] = pack2h(sc[2 * kc + 1][2], sc[2 * kc + 1][3]);
#pragma unroll
        for (int pr = 0; pr < 4; pr++) {
          uint32_t b4[4];
          int g = lane >> 3, r = lane & 7;
          int rv = kc * 16 + r + ((g & 1) ? 8 : 0);
          int cv = pr * 16 + ((g >= 2) ? 8 : 0);
          ldsm4t(b4, sma(SV(st) + rv * 72 + cv));
          mma_h(Oa[2 * pr], ap, b4[0], b4[1]);
          mma_h(Oa[2 * pr + 1], ap, b4[2], b4[3]);
        }
      }
    }
    __syncthreads();
  }
  // epilogue -> mix bf16 hi/lo planes
  float inv[2] = {1.f / lrow[0], 1.f / lrow[1]};
  bf16* mh = g_mixh + pl;
  bf16* ml = g_mixl + pl;
#pragma unroll
  for (int j = 0; j < 8; j++)
#pragma unroll
    for (int v = 0; v < 4; v++) {
      int ii = q0 + w * 16 + (lane >> 2) + ((v & 2) ? 8 : 0);
      int d = j * 8 + 2 * (lane & 3) + (v & 1);
      float val = Oa[j][v] * inv[v >> 1];
      bf16 hi = __float2bfloat16_rn(val);
      mh[(long)ii * D_ + d] = hi;
      ml[(long)ii * D_ + d] = __float2bfloat16_rn(val - __bfloat162float(hi));
    }
}

// ------------- launch -------------
extern "C" void kernel_launch(void* const* d_in, const int* in_sizes, int n_in,
                              void* d_out, int out_size) {
  const float* x = (const float*)d_in[0];
  const float* qkv = (const float*)d_in[1];
  const float* ow = (const float*)d_in[2];
  const float* rpe = (const float*)d_in[3];
  float* out = (float*)d_out;

  split_kernel<<<(MROWS * H_ + 255) / 256, 256>>>(x, MROWS * H_, 0);
  split_kernel<<<(H_ * QKVN + 255) / 256, 256>>>(qkv, H_ * QKVN, 1);
  split_kernel<<<(H_ * H_ + 255) / 256, 256>>>(ow, H_ * H_, 2);
  cumsum_kernel<<<16, 256>>>(rpe);
  gemm_kernel<0><<<dim3(QKVN / 64, MROWS / 128), 256>>>(nullptr);
  flash_kernel<<<dim3(16, B_ * N_), 256>>>();
  gemm_kernel<1><<<dim3(H_ / 64, MROWS / 128), 256>>>(out);
}

// round 6
// speedup vs baseline: 1.6691x; 1.3551x over previous
#include <cuda_runtime.h>
#include <cuda_bf16.h>
#include <cuda_fp16.h>
#include <cstdint>

#define DEVI __device__ __forceinline__
typedef __nv_bfloat16 bf16;

constexpr int B_ = 2, S_ = 2048, H_ = 1024, N_ = 16, D_ = 64;
constexpr int MROWS = B_ * S_;             // 4096
constexpr int QKVN = 3 * N_ * D_;          // 3072
constexpr long PLANE = (long)S_ * D_;      // 131072
constexpr long MPLANE = (long)B_ * N_ * PLANE;
constexpr float L2E = 1.4426950408889634f;

// ------------- static scratch -------------
__device__ __align__(16) __half g_xf[MROWS * H_];
__device__ __align__(16) __half g_wf[H_ * QKVN];
__device__ __align__(16) bf16 g_owh[H_ * H_];
__device__ __align__(16) bf16 g_owl[H_ * H_];
__device__ __align__(16) __half g_qkvf[3 * B_ * N_ * S_ * D_];
__device__ __align__(16) bf16 g_mixh[B_ * N_ * S_ * D_];
__device__ __align__(16) bf16 g_mixl[B_ * N_ * S_ * D_];
__device__ float g_cum[N_ * S_];

// ------------- helpers -------------
DEVI uint32_t sma(const void* p) { return (uint32_t)__cvta_generic_to_shared(p); }
DEVI void ldsm4(uint32_t r[4], uint32_t a) {
  asm volatile("ldmatrix.sync.aligned.m8n8.x4.shared.b16 {%0,%1,%2,%3},[%4];\n"
               : "=r"(r[0]), "=r"(r[1]), "=r"(r[2]), "=r"(r[3]) : "r"(a));
}
DEVI void ldsm4t(uint32_t r[4], uint32_t a) {
  asm volatile("ldmatrix.sync.aligned.m8n8.x4.trans.shared.b16 {%0,%1,%2,%3},[%4];\n"
               : "=r"(r[0]), "=r"(r[1]), "=r"(r[2]), "=r"(r[3]) : "r"(a));
}
DEVI void mma_bf(float c[4], const uint32_t a[4], uint32_t b0, uint32_t b1) {
  asm volatile(
      "mma.sync.aligned.m16n8k16.row.col.f32.bf16.bf16.f32 "
      "{%0,%1,%2,%3},{%4,%5,%6,%7},{%8,%9},{%0,%1,%2,%3};\n"
      : "+f"(c[0]), "+f"(c[1]), "+f"(c[2]), "+f"(c[3])
      : "r"(a[0]), "r"(a[1]), "r"(a[2]), "r"(a[3]), "r"(b0), "r"(b1));
}
DEVI void mma_h(float c[4], const uint32_t a[4], uint32_t b0, uint32_t b1) {
  asm volatile(
      "mma.sync.aligned.m16n8k16.row.col.f32.f16.f16.f32 "
      "{%0,%1,%2,%3},{%4,%5,%6,%7},{%8,%9},{%0,%1,%2,%3};\n"
      : "+f"(c[0]), "+f"(c[1]), "+f"(c[2]), "+f"(c[3])
      : "r"(a[0]), "r"(a[1]), "r"(a[2]), "r"(a[3]), "r"(b0), "r"(b1));
}
DEVI float e2(float x) { float r; asm("ex2.approx.f32 %0,%1;" : "=f"(r) : "f"(x)); return r; }
DEVI uint32_t pack2h(float lo, float hi) {
  __half2 h = __floats2half2_rn(lo, hi);
  uint32_t u; memcpy(&u, &h, 4); return u;
}
DEVI void cpa(uint32_t dst, const void* src) {
  asm volatile("cp.async.cg.shared.global [%0], [%1], 16;\n" :: "r"(dst), "l"(src));
}
DEVI void cpcommit() { asm volatile("cp.async.commit_group;\n"); }
template <int n> DEVI void cpwait() { asm volatile("cp.async.wait_group %0;\n" :: "n"(n)); }

// ------------- converts (globals referenced from DEVICE code only) -------------
__global__ void tohalf_kernel(const float* __restrict__ src, int n, int sel) {
  int i = blockIdx.x * blockDim.x + threadIdx.x;
  if (i >= n) return;
  __half* dst = (sel == 0) ? g_xf : g_wf;
  dst[i] = __float2half_rn(src[i]);
}
__global__ void split_ow_kernel(const float* __restrict__ src, int n) {
  int i = blockIdx.x * blockDim.x + threadIdx.x;
  if (i >= n) return;
  float v = src[i];
  bf16 hi = __float2bfloat16_rn(v);
  g_owh[i] = hi;
  g_owl[i] = __float2bfloat16_rn(v - __bfloat162float(hi));
}

// ------------- cumsum: one block per head -------------
__global__ void cumsum_kernel(const float* __restrict__ rpe) {
  int n = blockIdx.x, t = threadIdx.x, lane = t & 31, w = t >> 5;
  __shared__ float ws[8];
  float v[8];
  const float* row = rpe + n * S_;
#pragma unroll
  for (int j = 0; j < 8; j++) v[j] = row[t * 8 + j];
#pragma unroll
  for (int j = 1; j < 8; j++) v[j] += v[j - 1];
  float s = v[7];
#pragma unroll
  for (int o = 1; o < 32; o <<= 1) {
    float x = __shfl_up_sync(0xffffffffu, s, o);
    if (lane >= o) s += x;
  }
  if (lane == 31) ws[w] = s;
  __syncthreads();
  if (w == 0) {
    float x = (lane < 8) ? ws[lane] : 0.f;
#pragma unroll
    for (int o = 1; o < 8; o <<= 1) {
      float y = __shfl_up_sync(0xffffffffu, x, o);
      if (lane >= o) x += y;
    }
    if (lane < 8) ws[lane] = x;
  }
  __syncthreads();
  float off = s - v[7] + (w ? ws[w - 1] : 0.f);
#pragma unroll
  for (int j = 0; j < 8; j++) g_cum[n * S_ + t * 8 + j] = v[j] + off;
}

// ------------- QKV projection: single fp16 GEMM, cp.async 2-stage -------------
__global__ __launch_bounds__(256) void gemm_qkv_kernel() {
  __shared__ __align__(16) __half sA[2][128 * 24];
  __shared__ __align__(16) __half sB[2][16 * 72];

  const int tid = threadIdx.x, w = tid >> 5, lane = tid & 31;
  const int wm = w & 3, wn = w >> 2;
  const int row0 = blockIdx.y * 128, col0 = blockIdx.x * 64;

  float acc[2][4][4];
#pragma unroll
  for (int a = 0; a < 2; a++)
#pragma unroll
    for (int b = 0; b < 4; b++)
#pragma unroll
      for (int c = 0; c < 4; c++) acc[a][b][c] = 0.f;

  auto load_tile = [&](int st, int kt) {
    {
      int r = tid >> 1, seg = tid & 1;
      cpa(sma(&sA[st][r * 24 + seg * 8]), &g_xf[(long)(row0 + r) * H_ + kt + seg * 8]);
    }
    if (tid < 128) {
      int r = tid >> 3, c8 = tid & 7;
      cpa(sma(&sB[st][r * 72 + c8 * 8]), &g_wf[(long)(kt + r) * QKVN + col0 + c8 * 8]);
    }
  };

  load_tile(0, 0);
  cpcommit();
  constexpr int NK = H_ / 16;
  for (int t = 0; t < NK; t++) {
    if (t + 1 < NK) load_tile((t + 1) & 1, (t + 1) * 16);
    cpcommit();
    cpwait<1>();
    __syncthreads();
    const int st = t & 1;
    uint32_t af[2][4];
#pragma unroll
    for (int mi = 0; mi < 2; mi++) {
      int r = wm * 32 + mi * 16 + (lane & 15);
      ldsm4(af[mi], sma(&sA[st][r * 24 + (lane >> 4) * 8]));
    }
#pragma unroll
    for (int pr = 0; pr < 2; pr++) {
      uint32_t b4[4];
      int g = lane >> 3, r = lane & 7;
      int rb = r + ((g & 1) ? 8 : 0);
      int cb = wn * 32 + pr * 16 + ((g >= 2) ? 8 : 0);
      ldsm4t(b4, sma(&sB[st][rb * 72 + cb]));
#pragma unroll
      for (int mi = 0; mi < 2; mi++) {
        mma_h(acc[mi][2 * pr], af[mi], b4[0], b4[1]);
        mma_h(acc[mi][2 * pr + 1], af[mi], b4[2], b4[3]);
      }
    }
    __syncthreads();
  }
#pragma unroll
  for (int mi = 0; mi < 2; mi++)
#pragma unroll
    for (int nj = 0; nj < 4; nj++)
#pragma unroll
      for (int v = 0; v < 4; v++) {
        int rg = row0 + wm * 32 + mi * 16 + (lane >> 2) + ((v & 2) ? 8 : 0);
        int c = col0 + wn * 32 + nj * 8 + 2 * (lane & 3) + (v & 1);
        float val = acc[mi][nj][v];
        int m = c >> 10, nh = (c >> 6) & 15, d = c & 63;
        if (m == 0) val *= 0.125f;
        int b = rg >> 11, s = rg & 2047;
        long idx = ((long)(m * 32 + b * 16 + nh)) * PLANE + (long)s * D_ + d;
        g_qkvf[idx] = __float2half_rn(val);
      }
}

// ------------- out-projection: split-bf16 3-product, cp.async 2-stage -------------
__global__ __launch_bounds__(256) void gemm_out_kernel(float* __restrict__ outp) {
  __shared__ __align__(16) bf16 sA[2][2][128 * 24];
  __shared__ __align__(16) bf16 sB[2][2][16 * 72];

  const int tid = threadIdx.x, w = tid >> 5, lane = tid & 31;
  const int wm = w & 3, wn = w >> 2;
  const int row0 = blockIdx.y * 128, col0 = blockIdx.x * 64;

  float acc[2][4][4];
#pragma unroll
  for (int a = 0; a < 2; a++)
#pragma unroll
    for (int b = 0; b < 4; b++)
#pragma unroll
      for (int c = 0; c < 4; c++) acc[a][b][c] = 0.f;

  auto load_tile = [&](int st, int kt) {
    {
      int r = tid >> 1, seg = tid & 1;
      int rg = row0 + r;
      int k = kt + seg * 8;
      long off = ((long)((rg >> 11) * N_ + (k >> 6)) * S_ + (rg & 2047)) * D_ + (k & 63);
      cpa(sma(&sA[st][0][r * 24 + seg * 8]), &g_mixh[off]);
      cpa(sma(&sA[st][1][r * 24 + seg * 8]), &g_mixl[off]);
    }
    if (tid < 128) {
      int r = tid >> 3, c8 = tid & 7;
      long off = (long)(kt + r) * H_ + col0 + c8 * 8;
      cpa(sma(&sB[st][0][r * 72 + c8 * 8]), &g_owh[off]);
      cpa(sma(&sB[st][1][r * 72 + c8 * 8]), &g_owl[off]);
    }
  };

  load_tile(0, 0);
  cpcommit();
  constexpr int NK = H_ / 16;
  for (int t = 0; t < NK; t++) {
    if (t + 1 < NK) load_tile((t + 1) & 1, (t + 1) * 16);
    cpcommit();
    cpwait<1>();
    __syncthreads();
    const int st = t & 1;
    uint32_t afh[2][4], afl[2][4];
#pragma unroll
    for (int mi = 0; mi < 2; mi++) {
      int r = wm * 32 + mi * 16 + (lane & 15);
      int cc = (lane >> 4) * 8;
      ldsm4(afh[mi], sma(&sA[st][0][r * 24 + cc]));
      ldsm4(afl[mi], sma(&sA[st][1][r * 24 + cc]));
    }
#pragma unroll
    for (int pr = 0; pr < 2; pr++) {
      uint32_t bh4[4], bl4[4];
      int g = lane >> 3, r = lane & 7;
      int rb = r + ((g & 1) ? 8 : 0);
      int cb = wn * 32 + pr * 16 + ((g >= 2) ? 8 : 0);
      ldsm4t(bh4, sma(&sB[st][0][rb * 72 + cb]));
      ldsm4t(bl4, sma(&sB[st][1][rb * 72 + cb]));
#pragma unroll
      for (int mi = 0; mi < 2; mi++) {
        mma_bf(acc[mi][2 * pr], afh[mi], bh4[0], bh4[1]);
        mma_bf(acc[mi][2 * pr], afh[mi], bl4[0], bl4[1]);
        mma_bf(acc[mi][2 * pr], afl[mi], bh4[0], bh4[1]);
        mma_bf(acc[mi][2 * pr + 1], afh[mi], bh4[2], bh4[3]);
        mma_bf(acc[mi][2 * pr + 1], afh[mi], bl4[2], bl4[3]);
        mma_bf(acc[mi][2 * pr + 1], afl[mi], bh4[2], bh4[3]);
      }
    }
    __syncthreads();
  }
#pragma unroll
  for (int mi = 0; mi < 2; mi++)
#pragma unroll
    for (int nj = 0; nj < 4; nj++)
#pragma unroll
      for (int v = 0; v < 4; v++) {
        int rg = row0 + wm * 32 + mi * 16 + (lane >> 2) + ((v & 2) ? 8 : 0);
        int c = col0 + wn * 32 + nj * 8 + 2 * (lane & 3) + (v & 1);
        outp[(long)rg * H_ + c] = acc[mi][nj][v];
      }
}

// ------------- causal flash attention, fp16, cp.async 2-stage KV -------------
__global__ __launch_bounds__(256) void flash_kernel() {
  const int qt = 15 - blockIdx.x;
  const int bh = blockIdx.y;
  const int n = bh & 15;
  const int q0 = qt * 128;
  const int tid = threadIdx.x, w = tid >> 5, lane = tid & 31;

  __shared__ __align__(16) __half fsm[18432];  // 36 KB: Q overlaps KV ring
  __half* sQ = fsm;
#define SK(st) (fsm + (st) * 9216)
#define SV(st) (fsm + (st) * 9216 + 4608)

  const long pl = (long)bh * PLANE;
  const __half* qg = g_qkvf + pl;
  const __half* kg = g_qkvf + MPLANE + pl;
  const __half* vg = g_qkvf + 2 * MPLANE + pl;

#pragma unroll
  for (int p = 0; p < 4; p++) {
    int i = tid + 256 * p;
    int r = i >> 3, c8 = i & 7;
    *(uint4*)&sQ[r * 72 + c8 * 8] = *(const uint4*)&qg[(long)(q0 + r) * D_ + c8 * 8];
  }
  __syncthreads();
  uint32_t qf[4][4];
  {
    int r = w * 16 + (lane & 15), cb = (lane >> 4) * 8;
#pragma unroll
    for (int kc = 0; kc < 4; kc++) ldsm4(qf[kc], sma(&sQ[r * 72 + kc * 16 + cb]));
  }
  __syncthreads();

  float Oa[8][4];
#pragma unroll
  for (int j = 0; j < 8; j++)
#pragma unroll
    for (int v = 0; v < 4; v++) Oa[j][v] = 0.f;
  float mrow[2] = {-1e30f, -1e30f}, lrow[2] = {0.f, 0.f};
  const float* cumn = g_cum + n * S_;
  const int ntiles = 2 * qt + 2;
  const int itop = q0 + w * 16 + 15;

  auto loadkv = [&](int st, int t) {
    int kv0 = t * 64;
#pragma unroll
    for (int p = 0; p < 2; p++) {
      int i = tid + 256 * p;
      int r = i >> 3, c8 = i & 7;
      long g = (long)(kv0 + r) * D_ + c8 * 8;
      cpa(sma(SK(st) + r * 72 + c8 * 8), kg + g);
      cpa(sma(SV(st) + r * 72 + c8 * 8), vg + g);
    }
  };

  loadkv(0, 0);
  cpcommit();
  for (int t = 0; t < ntiles; t++) {
    if (t + 1 < ntiles) loadkv((t + 1) & 1, t + 1);
    cpcommit();
    cpwait<1>();
    __syncthreads();
    const int st = t & 1;
    const int kv0 = t * 64;
    if (kv0 <= itop) {
      float sc[8][4];
#pragma unroll
      for (int j = 0; j < 8; j++)
#pragma unroll
        for (int v = 0; v < 4; v++) sc[j][v] = 0.f;
#pragma unroll
      for (int kc = 0; kc < 4; kc++) {
#pragma unroll
        for (int pr = 0; pr < 4; pr++) {
          uint32_t b4[4];
          int g = lane >> 3, r = lane & 7;
          int rk = pr * 16 + r + ((g >= 2) ? 8 : 0);
          int ck = kc * 16 + ((g & 1) ? 8 : 0);
          ldsm4(b4, sma(SK(st) + rk * 72 + ck));
          mma_h(sc[2 * pr], qf[kc], b4[0], b4[1]);
          mma_h(sc[2 * pr + 1], qf[kc], b4[2], b4[3]);
        }
      }
      const int rb = q0 + w * 16 + (lane >> 2);
      const int cb = kv0 + 2 * (lane & 3);
      float mx[2] = {-1e30f, -1e30f};
#pragma unroll
      for (int j = 0; j < 8; j++)
#pragma unroll
        for (int v = 0; v < 4; v++) {
          int ii = rb + ((v & 2) ? 8 : 0);
          int jj = cb + j * 8 + (v & 1);
          int dlt = ii - jj;
          float s = (dlt < 0) ? -1e30f : sc[j][v] + __ldg(&cumn[dlt]);
          sc[j][v] = s;
          mx[v >> 1] = fmaxf(mx[v >> 1], s);
        }
#pragma unroll
      for (int h = 0; h < 2; h++) {
        mx[h] = fmaxf(mx[h], __shfl_xor_sync(0xffffffffu, mx[h], 1));
        mx[h] = fmaxf(mx[h], __shfl_xor_sync(0xffffffffu, mx[h], 2));
      }
      float al[2], sum[2] = {0.f, 0.f};
#pragma unroll
      for (int h = 0; h < 2; h++) {
        float mn = fmaxf(mrow[h], mx[h]);
        al[h] = e2((mrow[h] - mn) * L2E);
        mrow[h] = mn;
      }
#pragma unroll
      for (int j = 0; j < 8; j++)
#pragma unroll
        for (int v = 0; v < 4; v++) {
          float p = e2((sc[j][v] - mrow[v >> 1]) * L2E);
          sc[j][v] = p;
          sum[v >> 1] += p;
        }
#pragma unroll
      for (int h = 0; h < 2; h++) {
        sum[h] += __shfl_xor_sync(0xffffffffu, sum[h], 1);
        sum[h] += __shfl_xor_sync(0xffffffffu, sum[h], 2);
        lrow[h] = lrow[h] * al[h] + sum[h];
      }
#pragma unroll
      for (int j = 0; j < 8; j++)
#pragma unroll
        for (int v = 0; v < 4; v++) Oa[j][v] *= al[v >> 1];
#pragma unroll
      for (int kc = 0; kc < 4; kc++) {
        uint32_t ap[4];
        ap[0] = pack2h(sc[2 * kc][0], sc[2 * kc][1]);
        ap[1] = pack2h(sc[2 * kc][2], sc[2 * kc][3]);
        ap[2] = pack2h(sc[2 * kc + 1][0], sc[2 * kc + 1][1]);
        ap[3] = pack2h(sc[2 * kc + 1][2], sc[2 * kc + 1][3]);
#pragma unroll
        for (int pr = 0; pr < 4; pr++) {
          uint32_t b4[4];
          int g = lane >> 3, r = lane & 7;
          int rv = kc * 16 + r + ((g & 1) ? 8 : 0);
          int cv = pr * 16 + ((g >= 2) ? 8 : 0);
          ldsm4t(b4, sma(SV(st) + rv * 72 + cv));
          mma_h(Oa[2 * pr], ap, b4[0], b4[1]);
          mma_h(Oa[2 * pr + 1], ap, b4[2], b4[3]);
        }
      }
    }
    __syncthreads();
  }
  float inv[2] = {1.f / lrow[0], 1.f / lrow[1]};
  bf16* mh = g_mixh + pl;
  bf16* ml = g_mixl + pl;
#pragma unroll
  for (int j = 0; j < 8; j++)
#pragma unroll
    for (int v = 0; v < 4; v++) {
      int ii = q0 + w * 16 + (lane >> 2) + ((v & 2) ? 8 : 0);
      int d = j * 8 + 2 * (lane & 3) + (v & 1);
      float val = Oa[j][v] * inv[v >> 1];
      bf16 hi = __float2bfloat16_rn(val);
      mh[(long)ii * D_ + d] = hi;
      ml[(long)ii * D_ + d] = __float2bfloat16_rn(val - __bfloat162float(hi));
    }
}

// ------------- launch -------------
extern "C" void kernel_launch(void* const* d_in, const int* in_sizes, int n_in,
                              void* d_out, int out_size) {
  const float* x = (const float*)d_in[0];
  const float* qkv = (const float*)d_in[1];
  const float* ow = (const float*)d_in[2];
  const float* rpe = (const float*)d_in[3];
  float* out = (float*)d_out;

  tohalf_kernel<<<(MROWS * H_ + 255) / 256, 256>>>(x, MROWS * H_, 0);
  tohalf_kernel<<<(H_ * QKVN + 255) / 256, 256>>>(qkv, H_ * QKVN, 1);
  split_ow_kernel<<<(H_ * H_ + 255) / 256, 256>>>(ow, H_ * H_);
  cumsum_kernel<<<16, 256>>>(rpe);
  gemm_qkv_kernel<<<dim3(QKVN / 64, MROWS / 128), 256>>>();
  flash_kernel<<<dim3(16, B_ * N_), 256>>>();
  gemm_out_kernel<<<dim3(H_ / 64, MROWS / 128), 256>>>(out);
}

// round 9
// speedup vs baseline: 2.0489x; 1.2275x over previous
#include <cuda_runtime.h>
#include <cuda_bf16.h>
#include <cuda_fp16.h>
#include <cstdint>

#define DEVI __device__ __forceinline__
typedef __nv_bfloat16 bf16;

constexpr int B_ = 2, S_ = 2048, H_ = 1024, N_ = 16, D_ = 64;
constexpr int MROWS = B_ * S_;             // 4096
constexpr int QKVN = 3 * N_ * D_;          // 3072
constexpr long PLANE = (long)S_ * D_;      // 131072
constexpr long MPLANE = (long)B_ * N_ * PLANE;
constexpr float L2E = 1.4426950408889634f;

// ------------- static scratch -------------
__device__ __align__(16) __half g_xf[MROWS * H_];
__device__ __align__(16) __half g_wf[H_ * QKVN];
__device__ __align__(16) __half g_owf[H_ * H_];
__device__ __align__(16) __half g_qkvf[3 * B_ * N_ * S_ * D_];
__device__ __align__(16) __half g_mixf[B_ * N_ * S_ * D_];
__device__ float g_cum[N_ * S_];

// ------------- helpers -------------
DEVI uint32_t sma(const void* p) { return (uint32_t)__cvta_generic_to_shared(p); }
DEVI void ldsm4(uint32_t r[4], uint32_t a) {
  asm volatile("ldmatrix.sync.aligned.m8n8.x4.shared.b16 {%0,%1,%2,%3},[%4];\n"
               : "=r"(r[0]), "=r"(r[1]), "=r"(r[2]), "=r"(r[3]) : "r"(a));
}
DEVI void ldsm4t(uint32_t r[4], uint32_t a) {
  asm volatile("ldmatrix.sync.aligned.m8n8.x4.trans.shared.b16 {%0,%1,%2,%3},[%4];\n"
               : "=r"(r[0]), "=r"(r[1]), "=r"(r[2]), "=r"(r[3]) : "r"(a));
}
DEVI void mma_h(float c[4], const uint32_t a[4], uint32_t b0, uint32_t b1) {
  asm volatile(
      "mma.sync.aligned.m16n8k16.row.col.f32.f16.f16.f32 "
      "{%0,%1,%2,%3},{%4,%5,%6,%7},{%8,%9},{%0,%1,%2,%3};\n"
      : "+f"(c[0]), "+f"(c[1]), "+f"(c[2]), "+f"(c[3])
      : "r"(a[0]), "r"(a[1]), "r"(a[2]), "r"(a[3]), "r"(b0), "r"(b1));
}
DEVI float e2(float x) { float r; asm("ex2.approx.f32 %0,%1;" : "=f"(r) : "f"(x)); return r; }
DEVI uint32_t pack2h(float lo, float hi) {
  __half2 h = __floats2half2_rn(lo, hi);
  uint32_t u; memcpy(&u, &h, 4); return u;
}
DEVI void cpa(uint32_t dst, const void* src) {
  asm volatile("cp.async.cg.shared.global [%0], [%1], 16;\n" :: "r"(dst), "l"(src));
}
DEVI void cpcommit() { asm volatile("cp.async.commit_group;\n"); }
template <int n> DEVI void cpwait() { asm volatile("cp.async.wait_group %0;\n" :: "n"(n)); }

// ------------- converts (device-side global selection) -------------
__global__ void tohalf_kernel(const float* __restrict__ src, int n, int sel) {
  int i = (blockIdx.x * blockDim.x + threadIdx.x) * 4;
  if (i >= n) return;
  __half* dst = (sel == 0) ? g_xf : (sel == 1 ? g_wf : g_owf);
  float4 v = *(const float4*)&src[i];
  __half2 a = __floats2half2_rn(v.x, v.y);
  __half2 b = __floats2half2_rn(v.z, v.w);
  *(__half2*)&dst[i] = a;
  *(__half2*)&dst[i + 2] = b;
}

// ------------- cumsum: one block per head -------------
__global__ void cumsum_kernel(const float* __restrict__ rpe) {
  int n = blockIdx.x, t = threadIdx.x, lane = t & 31, w = t >> 5;
  __shared__ float ws[8];
  float v[8];
  const float* row = rpe + n * S_;
#pragma unroll
  for (int j = 0; j < 8; j++) v[j] = row[t * 8 + j];
#pragma unroll
  for (int j = 1; j < 8; j++) v[j] += v[j - 1];
  float s = v[7];
#pragma unroll
  for (int o = 1; o < 32; o <<= 1) {
    float x = __shfl_up_sync(0xffffffffu, s, o);
    if (lane >= o) s += x;
  }
  if (lane == 31) ws[w] = s;
  __syncthreads();
  if (w == 0) {
    float x = (lane < 8) ? ws[lane] : 0.f;
#pragma unroll
    for (int o = 1; o < 8; o <<= 1) {
      float y = __shfl_up_sync(0xffffffffu, x, o);
      if (lane >= o) x += y;
    }
    if (lane < 8) ws[lane] = x;
  }
  __syncthreads();
  float off = s - v[7] + (w ? ws[w - 1] : 0.f);
#pragma unroll
  for (int j = 0; j < 8; j++) g_cum[n * S_ + t * 8 + j] = v[j] + off;
}

// ------------- fp16 GEMM, cp.async 2-stage, K-step 16 -------------
// MODE 0: x[4096,1024]@w[1024,3072] -> fp16 q/k/v planes (q scaled 1/8)
// MODE 1: mix(planes)[4096,1024]@ow[1024,1024] -> fp32 d_out
template <int MODE>
__global__ __launch_bounds__(256) void gemm_kernel(float* __restrict__ outp) {
  constexpr int Nn = (MODE == 0) ? QKVN : H_;
  const __half* __restrict__ Ag = (MODE == 0) ? g_xf : g_mixf;
  const __half* __restrict__ Bg = (MODE == 0) ? g_wf : g_owf;

  __shared__ __align__(16) __half sA[2][128 * 24];
  __shared__ __align__(16) __half sB[2][16 * 72];

  const int tid = threadIdx.x, w = tid >> 5, lane = tid & 31;
  const int wm = w & 3, wn = w >> 2;
  const int row0 = blockIdx.y * 128, col0 = blockIdx.x * 64;

  float acc[2][4][4];
#pragma unroll
  for (int a = 0; a < 2; a++)
#pragma unroll
    for (int b = 0; b < 4; b++)
#pragma unroll
      for (int c = 0; c < 4; c++) acc[a][b][c] = 0.f;

  auto load_tile = [&](int st, int kt) {
    {
      int r = tid >> 1, seg = tid & 1;
      int rg = row0 + r;
      long off;
      if (MODE == 0) {
        off = (long)rg * H_ + kt + seg * 8;
      } else {
        int k = kt + seg * 8;
        off = ((long)((rg >> 11) * N_ + (k >> 6)) * S_ + (rg & 2047)) * D_ + (k & 63);
      }
      cpa(sma(&sA[st][r * 24 + seg * 8]), &Ag[off]);
    }
    if (tid < 128) {
      int r = tid >> 3, c8 = tid & 7;
      cpa(sma(&sB[st][r * 72 + c8 * 8]), &Bg[(long)(kt + r) * Nn + col0 + c8 * 8]);
    }
  };

  load_tile(0, 0);
  cpcommit();
  constexpr int NK = H_ / 16;
  for (int t = 0; t < NK; t++) {
    if (t + 1 < NK) load_tile((t + 1) & 1, (t + 1) * 16);
    cpcommit();
    cpwait<1>();
    __syncthreads();
    const int st = t & 1;
    uint32_t af[2][4];
#pragma unroll
    for (int mi = 0; mi < 2; mi++) {
      int r = wm * 32 + mi * 16 + (lane & 15);
      ldsm4(af[mi], sma(&sA[st][r * 24 + (lane >> 4) * 8]));
    }
#pragma unroll
    for (int pr = 0; pr < 2; pr++) {
      uint32_t b4[4];
      int g = lane >> 3, r = lane & 7;
      int rb = r + ((g & 1) ? 8 : 0);
      int cb = wn * 32 + pr * 16 + ((g >= 2) ? 8 : 0);
      ldsm4t(b4, sma(&sB[st][rb * 72 + cb]));
#pragma unroll
      for (int mi = 0; mi < 2; mi++) {
        mma_h(acc[mi][2 * pr], af[mi], b4[0], b4[1]);
        mma_h(acc[mi][2 * pr + 1], af[mi], b4[2], b4[3]);
      }
    }
    __syncthreads();
  }
#pragma unroll
  for (int mi = 0; mi < 2; mi++)
#pragma unroll
    for (int nj = 0; nj < 4; nj++)
#pragma unroll
      for (int v = 0; v < 4; v++) {
        int rg = row0 + wm * 32 + mi * 16 + (lane >> 2) + ((v & 2) ? 8 : 0);
        int c = col0 + wn * 32 + nj * 8 + 2 * (lane & 3) + (v & 1);
        float val = acc[mi][nj][v];
        if (MODE == 0) {
          int m = c >> 10, nh = (c >> 6) & 15, d = c & 63;
          if (m == 0) val *= 0.125f;
          int b = rg >> 11, s = rg & 2047;
          long idx = ((long)(m * 32 + b * 16 + nh)) * PLANE + (long)s * D_ + d;
          g_qkvf[idx] = __float2half_rn(val);
        } else {
          outp[(long)rg * H_ + c] = val;
        }
      }
}

// ------------- causal flash attention, fp16, cp.async 2-stage KV -------------
__global__ __launch_bounds__(256) void flash_kernel() {
  const int qt = 15 - blockIdx.x;
  const int bh = blockIdx.y;
  const int n = bh & 15;
  const int q0 = qt * 128;
  const int tid = threadIdx.x, w = tid >> 5, lane = tid & 31;

  __shared__ __align__(16) __half fsm[18432];  // 36 KB: Q overlaps KV ring
  __half* sQ = fsm;
#define SK(st) (fsm + (st) * 9216)
#define SV(st) (fsm + (st) * 9216 + 4608)

  const long pl = (long)bh * PLANE;
  const __half* qg = g_qkvf + pl;
  const __half* kg = g_qkvf + MPLANE + pl;
  const __half* vg = g_qkvf + 2 * MPLANE + pl;

#pragma unroll
  for (int p = 0; p < 4; p++) {
    int i = tid + 256 * p;
    int r = i >> 3, c8 = i & 7;
    *(uint4*)&sQ[r * 72 + c8 * 8] = *(const uint4*)&qg[(long)(q0 + r) * D_ + c8 * 8];
  }
  __syncthreads();
  uint32_t qf[4][4];
  {
    int r = w * 16 + (lane & 15), cb = (lane >> 4) * 8;
#pragma unroll
    for (int kc = 0; kc < 4; kc++) ldsm4(qf[kc], sma(&sQ[r * 72 + kc * 16 + cb]));
  }
  __syncthreads();

  float Oa[8][4];
#pragma unroll
  for (int j = 0; j < 8; j++)
#pragma unroll
    for (int v = 0; v < 4; v++) Oa[j][v] = 0.f;
  float mrow[2] = {-1e30f, -1e30f}, lrow[2] = {0.f, 0.f};
  const float* cumn = g_cum + n * S_;
  const int ntiles = 2 * qt + 2;
  const int itop = q0 + w * 16 + 15;

  auto loadkv = [&](int st, int t) {
    int kv0 = t * 64;
#pragma unroll
    for (int p = 0; p < 2; p++) {
      int i = tid + 256 * p;
      int r = i >> 3, c8 = i & 7;
      long g = (long)(kv0 + r) * D_ + c8 * 8;
      cpa(sma(SK(st) + r * 72 + c8 * 8), kg + g);
      cpa(sma(SV(st) + r * 72 + c8 * 8), vg + g);
    }
  };

  loadkv(0, 0);
  cpcommit();
  for (int t = 0; t < ntiles; t++) {
    if (t + 1 < ntiles) loadkv((t + 1) & 1, t + 1);
    cpcommit();
    cpwait<1>();
    __syncthreads();
    const int st = t & 1;
    const int kv0 = t * 64;
    if (kv0 <= itop) {
      float sc[8][4];
#pragma unroll
      for (int j = 0; j < 8; j++)
#pragma unroll
        for (int v = 0; v < 4; v++) sc[j][v] = 0.f;
#pragma unroll
      for (int kc = 0; kc < 4; kc++) {
#pragma unroll
        for (int pr = 0; pr < 4; pr++) {
          uint32_t b4[4];
          int g = lane >> 3, r = lane & 7;
          int rk = pr * 16 + r + ((g >= 2) ? 8 : 0);
          int ck = kc * 16 + ((g & 1) ? 8 : 0);
          ldsm4(b4, sma(SK(st) + rk * 72 + ck));
          mma_h(sc[2 * pr], qf[kc], b4[0], b4[1]);
          mma_h(sc[2 * pr + 1], qf[kc], b4[2], b4[3]);
        }
      }
      const int rb = q0 + w * 16 + (lane >> 2);
      const int cb = kv0 + 2 * (lane & 3);
      float mx[2] = {-1e30f, -1e30f};
#pragma unroll
      for (int j = 0; j < 8; j++)
#pragma unroll
        for (int v = 0; v < 4; v++) {
          int ii = rb + ((v & 2) ? 8 : 0);
          int jj = cb + j * 8 + (v & 1);
          int dlt = ii - jj;
          float s = (dlt < 0) ? -1e30f : sc[j][v] + __ldg(&cumn[dlt]);
          sc[j][v] = s;
          mx[v >> 1] = fmaxf(mx[v >> 1], s);
        }
#pragma unroll
      for (int h = 0; h < 2; h++) {
        mx[h] = fmaxf(mx[h], __shfl_xor_sync(0xffffffffu, mx[h], 1));
        mx[h] = fmaxf(mx[h], __shfl_xor_sync(0xffffffffu, mx[h], 2));
      }
      float al[2], sum[2] = {0.f, 0.f};
#pragma unroll
      for (int h = 0; h < 2; h++) {
        float mn = fmaxf(mrow[h], mx[h]);
        al[h] = e2((mrow[h] - mn) * L2E);
        mrow[h] = mn;
      }
#pragma unroll
      for (int j = 0; j < 8; j++)
#pragma unroll
        for (int v = 0; v < 4; v++) {
          float p = e2((sc[j][v] - mrow[v >> 1]) * L2E);
          sc[j][v] = p;
          sum[v >> 1] += p;
        }
#pragma unroll
      for (int h = 0; h < 2; h++) {
        sum[h] += __shfl_xor_sync(0xffffffffu, sum[h], 1);
        sum[h] += __shfl_xor_sync(0xffffffffu, sum[h], 2);
        lrow[h] = lrow[h] * al[h] + sum[h];
      }
#pragma unroll
      for (int j = 0; j < 8; j++)
#pragma unroll
        for (int v = 0; v < 4; v++) Oa[j][v] *= al[v >> 1];
#pragma unroll
      for (int kc = 0; kc < 4; kc++) {
        uint32_t ap[4];
        ap[0] = pack2h(sc[2 * kc][0], sc[2 * kc][1]);
        ap[1] = pack2h(sc[2 * kc][2], sc[2 * kc][3]);
        ap[2] = pack2h(sc[2 * kc + 1][0], sc[2 * kc + 1][1]);
        ap[3] = pack2h(sc[2 * kc + 1][2], sc[2 * kc + 1][3]);
#pragma unroll
        for (int pr = 0; pr < 4; pr++) {
          uint32_t b4[4];
          int g = lane >> 3, r = lane & 7;
          int rv = kc * 16 + r + ((g & 1) ? 8 : 0);
          int cv = pr * 16 + ((g >= 2) ? 8 : 0);
          ldsm4t(b4, sma(SV(st) + rv * 72 + cv));
          mma_h(Oa[2 * pr], ap, b4[0], b4[1]);
          mma_h(Oa[2 * pr + 1], ap, b4[2], b4[3]);
        }
      }
    }
    __syncthreads();
  }
  float inv[2] = {1.f / lrow[0], 1.f / lrow[1]};
  __half* mf = g_mixf + pl;
#pragma unroll
  for (int j = 0; j < 8; j++)
#pragma unroll
    for (int v = 0; v < 2; v++) {  // two half2 stores per j (rows +0 and +8)
      int ii = q0 + w * 16 + (lane >> 2) + v * 8;
      int d = j * 8 + 2 * (lane & 3);
      __half2 h = __floats2half2_rn(Oa[j][2 * v] * inv[v], Oa[j][2 * v + 1] * inv[v]);
      *(__half2*)&mf[(long)ii * D_ + d] = h;
    }
}

// ------------- launch -------------
extern "C" void kernel_launch(void* const* d_in, const int* in_sizes, int n_in,
                              void* d_out, int out_size) {
  const float* x = (const float*)d_in[0];
  const float* qkv = (const float*)d_in[1];
  const float* ow = (const float*)d_in[2];
  const float* rpe = (const float*)d_in[3];
  float* out = (float*)d_out;

  tohalf_kernel<<<(MROWS * H_ / 4 + 255) / 256, 256>>>(x, MROWS * H_, 0);
  tohalf_kernel<<<(H_ * QKVN / 4 + 255) / 256, 256>>>(qkv, H_ * QKVN, 1);
  tohalf_kernel<<<(H_ * H_ / 4 + 255) / 256, 256>>>(ow, H_ * H_, 2);
  cumsum_kernel<<<16, 256>>>(rpe);
  gemm_kernel<0><<<dim3(QKVN / 64, MROWS / 128), 256>>>(nullptr);
  flash_kernel<<<dim3(16, B_ * N_), 256>>>();
  gemm_kernel<1><<<dim3(H_ / 64, MROWS / 128), 256>>>(out);
}

// round 10
// speedup vs baseline: 2.4673x; 1.2042x over previous
#include <cuda_runtime.h>
#include <cuda_bf16.h>
#include <cuda_fp16.h>
#include <cstdint>

#define DEVI __device__ __forceinline__

constexpr int B_ = 2, S_ = 2048, H_ = 1024, N_ = 16, D_ = 64;
constexpr int MROWS = B_ * S_;             // 4096
constexpr int QKVN = 3 * N_ * D_;          // 3072
constexpr long PLANE = (long)S_ * D_;      // 131072
constexpr long MPLANE = (long)B_ * N_ * PLANE;
constexpr float L2E = 1.4426950408889634f;
constexpr int XN = MROWS * H_;             // 4194304
constexpr int WN = H_ * QKVN;              // 3145728
constexpr int OWN = H_ * H_;               // 1048576

// ------------- static scratch -------------
__device__ __align__(16) __half g_xf[XN];
__device__ __align__(16) __half g_wf[WN];
__device__ __align__(16) __half g_owf[OWN];
__device__ __align__(16) __half g_qkvf[3 * B_ * N_ * S_ * D_];
__device__ __align__(16) __half g_mixf[B_ * N_ * S_ * D_];
__device__ float g_cum[N_ * S_];           // pre-scaled by L2E

// ------------- helpers -------------
DEVI uint32_t sma(const void* p) { return (uint32_t)__cvta_generic_to_shared(p); }
DEVI void ldsm4(uint32_t r[4], uint32_t a) {
  asm volatile("ldmatrix.sync.aligned.m8n8.x4.shared.b16 {%0,%1,%2,%3},[%4];\n"
               : "=r"(r[0]), "=r"(r[1]), "=r"(r[2]), "=r"(r[3]) : "r"(a));
}
DEVI void ldsm4t(uint32_t r[4], uint32_t a) {
  asm volatile("ldmatrix.sync.aligned.m8n8.x4.trans.shared.b16 {%0,%1,%2,%3},[%4];\n"
               : "=r"(r[0]), "=r"(r[1]), "=r"(r[2]), "=r"(r[3]) : "r"(a));
}
DEVI void mma_h(float c[4], const uint32_t a[4], uint32_t b0, uint32_t b1) {
  asm volatile(
      "mma.sync.aligned.m16n8k16.row.col.f32.f16.f16.f32 "
      "{%0,%1,%2,%3},{%4,%5,%6,%7},{%8,%9},{%0,%1,%2,%3};\n"
      : "+f"(c[0]), "+f"(c[1]), "+f"(c[2]), "+f"(c[3])
      : "r"(a[0]), "r"(a[1]), "r"(a[2]), "r"(a[3]), "r"(b0), "r"(b1));
}
DEVI float e2(float x) { float r; asm("ex2.approx.f32 %0,%1;" : "=f"(r) : "f"(x)); return r; }
DEVI uint32_t pack2h(float lo, float hi) {
  __half2 h = __floats2half2_rn(lo, hi);
  uint32_t u; memcpy(&u, &h, 4); return u;
}
DEVI void cpa(uint32_t dst, const void* src) {
  asm volatile("cp.async.cg.shared.global [%0], [%1], 16;\n" :: "r"(dst), "l"(src));
}
DEVI void cpcommit() { asm volatile("cp.async.commit_group;\n"); }
template <int n> DEVI void cpwait() { asm volatile("cp.async.wait_group %0;\n" :: "n"(n)); }

// ------------- fused convert: x, qkv-w, ow -> fp16 -------------
__global__ void convert_all_kernel(const float* __restrict__ x,
                                   const float* __restrict__ qkv,
                                   const float* __restrict__ ow) {
  long i = (long)(blockIdx.x * blockDim.x + threadIdx.x) * 4;
  const float* src;
  __half* dst;
  long off;
  if (i < XN) { src = x; dst = g_xf; off = i; }
  else if (i < XN + WN) { src = qkv; dst = g_wf; off = i - XN; }
  else if (i < XN + WN + OWN) { src = ow; dst = g_owf; off = i - XN - WN; }
  else return;
  float4 v = *(const float4*)&src[off];
  *(__half2*)&dst[off] = __floats2half2_rn(v.x, v.y);
  *(__half2*)&dst[off + 2] = __floats2half2_rn(v.z, v.w);
}

// ------------- cumsum (scaled by L2E): one block per head -------------
__global__ void cumsum_kernel(const float* __restrict__ rpe) {
  int n = blockIdx.x, t = threadIdx.x, lane = t & 31, w = t >> 5;
  __shared__ float ws[8];
  float v[8];
  const float* row = rpe + n * S_;
#pragma unroll
  for (int j = 0; j < 8; j++) v[j] = row[t * 8 + j];
#pragma unroll
  for (int j = 1; j < 8; j++) v[j] += v[j - 1];
  float s = v[7];
#pragma unroll
  for (int o = 1; o < 32; o <<= 1) {
    float x = __shfl_up_sync(0xffffffffu, s, o);
    if (lane >= o) s += x;
  }
  if (lane == 31) ws[w] = s;
  __syncthreads();
  if (w == 0) {
    float x = (lane < 8) ? ws[lane] : 0.f;
#pragma unroll
    for (int o = 1; o < 8; o <<= 1) {
      float y = __shfl_up_sync(0xffffffffu, x, o);
      if (lane >= o) x += y;
    }
    if (lane < 8) ws[lane] = x;
  }
  __syncthreads();
  float off = s - v[7] + (w ? ws[w - 1] : 0.f);
#pragma unroll
  for (int j = 0; j < 8; j++) g_cum[n * S_ + t * 8 + j] = (v[j] + off) * L2E;
}

// ------------- fp16 GEMM, cp.async 2-stage, K-step 32 -------------
// MODE 0: x[4096,1024]@w[1024,3072] -> fp16 q/k/v planes (q scaled L2E/8)
// MODE 1: mix(planes)[4096,1024]@ow[1024,1024] -> fp32 d_out
template <int MODE>
__global__ __launch_bounds__(256) void gemm_kernel(float* __restrict__ outp) {
  constexpr int Nn = (MODE == 0) ? QKVN : H_;
  const __half* __restrict__ Ag = (MODE == 0) ? g_xf : g_mixf;
  const __half* __restrict__ Bg = (MODE == 0) ? g_wf : g_owf;

  __shared__ __align__(16) __half sA[2][128 * 40];  // 128 x 32 (pad 40)
  __shared__ __align__(16) __half sB[2][32 * 72];   // 32 x 64 (pad 72)

  const int tid = threadIdx.x, w = tid >> 5, lane = tid & 31;
  const int wm = w & 3, wn = w >> 2;
  const int row0 = blockIdx.y * 128, col0 = blockIdx.x * 64;

  float acc[2][4][4];
#pragma unroll
  for (int a = 0; a < 2; a++)
#pragma unroll
    for (int b = 0; b < 4; b++)
#pragma unroll
      for (int c = 0; c < 4; c++) acc[a][b][c] = 0.f;

  auto load_tile = [&](int st, int kt) {
#pragma unroll
    for (int p = 0; p < 2; p++) {  // A 128x32
      int i = tid + 256 * p;
      int r = i >> 2, seg = i & 3;
      int rg = row0 + r;
      long off;
      if (MODE == 0) {
        off = (long)rg * H_ + kt + seg * 8;
      } else {
        int k = kt + seg * 8;
        off = ((long)((rg >> 11) * N_ + (k >> 6)) * S_ + (rg & 2047)) * D_ + (k & 63);
      }
      cpa(sma(&sA[st][r * 40 + seg * 8]), &Ag[off]);
    }
    {  // B 32x64
      int r = tid >> 3, c8 = tid & 7;
      cpa(sma(&sB[st][r * 72 + c8 * 8]), &Bg[(long)(kt + r) * Nn + col0 + c8 * 8]);
    }
  };

  load_tile(0, 0);
  cpcommit();
  constexpr int NK = H_ / 32;
  for (int t = 0; t < NK; t++) {
    if (t + 1 < NK) load_tile((t + 1) & 1, (t + 1) * 32);
    cpcommit();
    cpwait<1>();
    __syncthreads();
    const int st = t & 1;
#pragma unroll
    for (int kc = 0; kc < 2; kc++) {
      uint32_t af[2][4];
#pragma unroll
      for (int mi = 0; mi < 2; mi++) {
        int r = wm * 32 + mi * 16 + (lane & 15);
        ldsm4(af[mi], sma(&sA[st][r * 40 + kc * 16 + (lane >> 4) * 8]));
      }
#pragma unroll
      for (int pr = 0; pr < 2; pr++) {
        uint32_t b4[4];
        int g = lane >> 3, r = lane & 7;
        int rb = kc * 16 + r + ((g & 1) ? 8 : 0);
        int cb = wn * 32 + pr * 16 + ((g >= 2) ? 8 : 0);
        ldsm4t(b4, sma(&sB[st][rb * 72 + cb]));
#pragma unroll
        for (int mi = 0; mi < 2; mi++) {
          mma_h(acc[mi][2 * pr], af[mi], b4[0], b4[1]);
          mma_h(acc[mi][2 * pr + 1], af[mi], b4[2], b4[3]);
        }
      }
    }
    __syncthreads();
  }
#pragma unroll
  for (int mi = 0; mi < 2; mi++)
#pragma unroll
    for (int nj = 0; nj < 4; nj++)
#pragma unroll
      for (int v = 0; v < 4; v++) {
        int rg = row0 + wm * 32 + mi * 16 + (lane >> 2) + ((v & 2) ? 8 : 0);
        int c = col0 + wn * 32 + nj * 8 + 2 * (lane & 3) + (v & 1);
        float val = acc[mi][nj][v];
        if (MODE == 0) {
          int m = c >> 10, nh = (c >> 6) & 15, d = c & 63;
          if (m == 0) val *= 0.125f * L2E;  // fold D^-0.5 and log2(e)
          int b = rg >> 11, s = rg & 2047;
          long idx = ((long)(m * 32 + b * 16 + nh)) * PLANE + (long)s * D_ + d;
          g_qkvf[idx] = __float2half_rn(val);
        } else {
          outp[(long)rg * H_ + c] = val;
        }
      }
}

// ------------- causal flash attention, fp16, smem bias window -------------
__global__ __launch_bounds__(256) void flash_kernel() {
  const int qt = 15 - blockIdx.x;
  const int bh = blockIdx.y;
  const int n = bh & 15;
  const int q0 = qt * 128;
  const int tid = threadIdx.x, w = tid >> 5, lane = tid & 31;

  __shared__ __align__(16) __half fsm[18432];  // 36 KB: Q overlaps KV ring
  __shared__ float sBias[192];
  __half* sQ = fsm;
#define SK(st) (fsm + (st) * 9216)
#define SV(st) (fsm + (st) * 9216 + 4608)

  const long pl = (long)bh * PLANE;
  const __half* qg = g_qkvf + pl;
  const __half* kg = g_qkvf + MPLANE + pl;
  const __half* vg = g_qkvf + 2 * MPLANE + pl;

#pragma unroll
  for (int p = 0; p < 4; p++) {
    int i = tid + 256 * p;
    int r = i >> 3, c8 = i & 7;
    *(uint4*)&sQ[r * 72 + c8 * 8] = *(const uint4*)&qg[(long)(q0 + r) * D_ + c8 * 8];
  }
  __syncthreads();
  uint32_t qf[4][4];
  {
    int r = w * 16 + (lane & 15), cb = (lane >> 4) * 8;
#pragma unroll
    for (int kc = 0; kc < 4; kc++) ldsm4(qf[kc], sma(&sQ[r * 72 + kc * 16 + cb]));
  }
  __syncthreads();

  float Oa[8][4];
#pragma unroll
  for (int j = 0; j < 8; j++)
#pragma unroll
    for (int v = 0; v < 4; v++) Oa[j][v] = 0.f;
  float mrow[2] = {-1e30f, -1e30f}, lrow[2] = {0.f, 0.f};
  const float* cumn = g_cum + n * S_;
  const int ntiles = 2 * qt + 2;
  const int itop = q0 + w * 16 + 15;
  // per-thread bias base: idx = ibase + (row8 ? 8 : 0) - j*8 - (v&1)
  const int ibase = w * 16 + (lane >> 2) + 63 - 2 * (lane & 3);

  auto loadkv = [&](int st, int t) {
    int kv0 = t * 64;
#pragma unroll
    for (int p = 0; p < 2; p++) {
      int i = tid + 256 * p;
      int r = i >> 3, c8 = i & 7;
      long g = (long)(kv0 + r) * D_ + c8 * 8;
      cpa(sma(SK(st) + r * 72 + c8 * 8), kg + g);
      cpa(sma(SV(st) + r * 72 + c8 * 8), vg + g);
    }
  };

  loadkv(0, 0);
  cpcommit();
  for (int t = 0; t < ntiles; t++) {
    const int kv0 = t * 64;
    if (t + 1 < ntiles) loadkv((t + 1) & 1, t + 1);
    cpcommit();
    // stage bias window: sBias[i] = cum[q0-kv0-63+i], i in [0,192)
    {
      int base = q0 - kv0 - 63;
      if (tid < 192) {
        int src = base + tid;
        sBias[tid] = (src >= 0) ? cumn[src] : 0.f;
      }
    }
    cpwait<1>();
    __syncthreads();
    const int st = t & 1;
    if (kv0 <= itop) {
      float sc[8][4];
#pragma unroll
      for (int j = 0; j < 8; j++)
#pragma unroll
        for (int v = 0; v < 4; v++) sc[j][v] = 0.f;
#pragma unroll
      for (int kc = 0; kc < 4; kc++) {
#pragma unroll
        for (int pr = 0; pr < 4; pr++) {
          uint32_t b4[4];
          int g = lane >> 3, r = lane & 7;
          int rk = pr * 16 + r + ((g >= 2) ? 8 : 0);
          int ck = kc * 16 + ((g & 1) ? 8 : 0);
          ldsm4(b4, sma(SK(st) + rk * 72 + ck));
          mma_h(sc[2 * pr], qf[kc], b4[0], b4[1]);
          mma_h(sc[2 * pr + 1], qf[kc], b4[2], b4[3]);
        }
      }
      // bias + mask + online softmax (log2 domain; L2E pre-folded)
      const bool full = (kv0 + 63 <= q0 + w * 16);
      const int dshift = q0 - kv0 - 63;  // global delta = dshift + idx
      float mx[2] = {-1e30f, -1e30f};
      if (full) {
#pragma unroll
        for (int j = 0; j < 8; j++)
#pragma unroll
          for (int v = 0; v < 4; v++) {
            int idx = ibase + ((v & 2) ? 8 : 0) - j * 8 - (v & 1);
            float s = sc[j][v] + sBias[idx];
            sc[j][v] = s;
            mx[v >> 1] = fmaxf(mx[v >> 1], s);
          }
      } else {
#pragma unroll
        for (int j = 0; j < 8; j++)
#pragma unroll
          for (int v = 0; v < 4; v++) {
            int idx = ibase + ((v & 2) ? 8 : 0) - j * 8 - (v & 1);
            float s = (dshift + idx < 0) ? -1e30f : sc[j][v] + sBias[idx];
            sc[j][v] = s;
            mx[v >> 1] = fmaxf(mx[v >> 1], s);
          }
      }
#pragma unroll
      for (int h = 0; h < 2; h++) {
        mx[h] = fmaxf(mx[h], __shfl_xor_sync(0xffffffffu, mx[h], 1));
        mx[h] = fmaxf(mx[h], __shfl_xor_sync(0xffffffffu, mx[h], 2));
      }
      float al[2], sum[2] = {0.f, 0.f};
#pragma unroll
      for (int h = 0; h < 2; h++) {
        float mn = fmaxf(mrow[h], mx[h]);
        al[h] = e2(mrow[h] - mn);
        mrow[h] = mn;
      }
#pragma unroll
      for (int j = 0; j < 8; j++)
#pragma unroll
        for (int v = 0; v < 4; v++) {
          float p = e2(sc[j][v] - mrow[v >> 1]);
          sc[j][v] = p;
          sum[v >> 1] += p;
        }
#pragma unroll
      for (int h = 0; h < 2; h++) {
        sum[h] += __shfl_xor_sync(0xffffffffu, sum[h], 1);
        sum[h] += __shfl_xor_sync(0xffffffffu, sum[h], 2);
        lrow[h] = lrow[h] * al[h] + sum[h];
      }
#pragma unroll
      for (int j = 0; j < 8; j++)
#pragma unroll
        for (int v = 0; v < 4; v++) Oa[j][v] *= al[v >> 1];
#pragma unroll
      for (int kc = 0; kc < 4; kc++) {
        uint32_t ap[4];
        ap[0] = pack2h(sc[2 * kc][0], sc[2 * kc][1]);
        ap[1] = pack2h(sc[2 * kc][2], sc[2 * kc][3]);
        ap[2] = pack2h(sc[2 * kc + 1][0], sc[2 * kc + 1][1]);
        ap[3] = pack2h(sc[2 * kc + 1][2], sc[2 * kc + 1][3]);
#pragma unroll
        for (int pr = 0; pr < 4; pr++) {
          uint32_t b4[4];
          int g = lane >> 3, r = lane & 7;
          int rv = kc * 16 + r + ((g & 1) ? 8 : 0);
          int cv = pr * 16 + ((g >= 2) ? 8 : 0);
          ldsm4t(b4, sma(SV(st) + rv * 72 + cv));
          mma_h(Oa[2 * pr], ap, b4[0], b4[1]);
          mma_h(Oa[2 * pr + 1], ap, b4[2], b4[3]);
        }
      }
    }
    __syncthreads();
  }
  float inv[2] = {1.f / lrow[0], 1.f / lrow[1]};
  __half* mf = g_mixf + pl;
#pragma unroll
  for (int j = 0; j < 8; j++)
#pragma unroll
    for (int v = 0; v < 2; v++) {
      int ii = q0 + w * 16 + (lane >> 2) + v * 8;
      int d = j * 8 + 2 * (lane & 3);
      __half2 h = __floats2half2_rn(Oa[j][2 * v] * inv[v], Oa[j][2 * v + 1] * inv[v]);
      *(__half2*)&mf[(long)ii * D_ + d] = h;
    }
}

// ------------- launch -------------
extern "C" void kernel_launch(void* const* d_in, const int* in_sizes, int n_in,
                              void* d_out, int out_size) {
  const float* x = (const float*)d_in[0];
  const float* qkv = (const float*)d_in[1];
  const float* ow = (const float*)d_in[2];
  const float* rpe = (const float*)d_in[3];
  float* out = (float*)d_out;

  convert_all_kernel<<<(XN + WN + OWN) / 4 / 256, 256>>>(x, qkv, ow);
  cumsum_kernel<<<16, 256>>>(rpe);
  gemm_kernel<0><<<dim3(QKVN / 64, MROWS / 128), 256>>>(nullptr);
  flash_kernel<<<dim3(16, B_ * N_), 256>>>();
  gemm_kernel<1><<<dim3(H_ / 64, MROWS / 128), 256>>>(out);
}

// round 11
// speedup vs baseline: 2.5985x; 1.0532x over previous
#include <cuda_runtime.h>
#include <cuda_bf16.h>
#include <cuda_fp16.h>
#include <cstdint>

#define DEVI __device__ __forceinline__

constexpr int B_ = 2, S_ = 2048, H_ = 1024, N_ = 16, D_ = 64;
constexpr int MROWS = B_ * S_;             // 4096
constexpr int QKVN = 3 * N_ * D_;          // 3072
constexpr long PLANE = (long)S_ * D_;      // 131072
constexpr long MPLANE = (long)B_ * N_ * PLANE;
constexpr float L2E = 1.4426950408889634f;
constexpr int XN = MROWS * H_;
constexpr int WN = H_ * QKVN;
constexpr int OWN = H_ * H_;

// ------------- static scratch -------------
__device__ __align__(16) __half g_xf[XN];
__device__ __align__(16) __half g_wf[WN];
__device__ __align__(16) __half g_owf[OWN];
__device__ __align__(16) __half g_qkvf[3 * B_ * N_ * S_ * D_];
__device__ __align__(16) __half g_mixf[B_ * N_ * S_ * D_];
__device__ float g_cum[N_ * S_];           // pre-scaled by L2E

// ------------- helpers -------------
DEVI uint32_t sma(const void* p) { return (uint32_t)__cvta_generic_to_shared(p); }
DEVI void ldsm4(uint32_t r[4], uint32_t a) {
  asm volatile("ldmatrix.sync.aligned.m8n8.x4.shared.b16 {%0,%1,%2,%3},[%4];\n"
               : "=r"(r[0]), "=r"(r[1]), "=r"(r[2]), "=r"(r[3]) : "r"(a));
}
DEVI void ldsm4t(uint32_t r[4], uint32_t a) {
  asm volatile("ldmatrix.sync.aligned.m8n8.x4.trans.shared.b16 {%0,%1,%2,%3},[%4];\n"
               : "=r"(r[0]), "=r"(r[1]), "=r"(r[2]), "=r"(r[3]) : "r"(a));
}
DEVI void mma_h(float c[4], const uint32_t a[4], uint32_t b0, uint32_t b1) {
  asm volatile(
      "mma.sync.aligned.m16n8k16.row.col.f32.f16.f16.f32 "
      "{%0,%1,%2,%3},{%4,%5,%6,%7},{%8,%9},{%0,%1,%2,%3};\n"
      : "+f"(c[0]), "+f"(c[1]), "+f"(c[2]), "+f"(c[3])
      : "r"(a[0]), "r"(a[1]), "r"(a[2]), "r"(a[3]), "r"(b0), "r"(b1));
}
DEVI float e2(float x) { float r; asm("ex2.approx.f32 %0,%1;" : "=f"(r) : "f"(x)); return r; }
DEVI uint32_t pack2h(float lo, float hi) {
  __half2 h = __floats2half2_rn(lo, hi);
  uint32_t u; memcpy(&u, &h, 4); return u;
}
DEVI uint32_t h2ex2(uint32_t x) {
  uint32_t r; asm("ex2.approx.f16x2 %0,%1;" : "=r"(r) : "r"(x)); return r;
}
DEVI void cpa(uint32_t dst, const void* src) {
  asm volatile("cp.async.cg.shared.global [%0], [%1], 16;\n" :: "r"(dst), "l"(src));
}
DEVI void cpcommit() { asm volatile("cp.async.commit_group;\n"); }
template <int n> DEVI void cpwait() { asm volatile("cp.async.wait_group %0;\n" :: "n"(n)); }

// ------------- fused convert -------------
__global__ void convert_all_kernel(const float* __restrict__ x,
                                   const float* __restrict__ qkv,
                                   const float* __restrict__ ow) {
  long i = (long)(blockIdx.x * blockDim.x + threadIdx.x) * 4;
  const float* src;
  __half* dst;
  long off;
  if (i < XN) { src = x; dst = g_xf; off = i; }
  else if (i < XN + WN) { src = qkv; dst = g_wf; off = i - XN; }
  else if (i < XN + WN + OWN) { src = ow; dst = g_owf; off = i - XN - WN; }
  else return;
  float4 v = *(const float4*)&src[off];
  *(__half2*)&dst[off] = __floats2half2_rn(v.x, v.y);
  *(__half2*)&dst[off + 2] = __floats2half2_rn(v.z, v.w);
}

// ------------- cumsum (scaled by L2E) -------------
__global__ void cumsum_kernel(const float* __restrict__ rpe) {
  int n = blockIdx.x, t = threadIdx.x, lane = t & 31, w = t >> 5;
  __shared__ float ws[8];
  float v[8];
  const float* row = rpe + n * S_;
#pragma unroll
  for (int j = 0; j < 8; j++) v[j] = row[t * 8 + j];
#pragma unroll
  for (int j = 1; j < 8; j++) v[j] += v[j - 1];
  float s = v[7];
#pragma unroll
  for (int o = 1; o < 32; o <<= 1) {
    float x = __shfl_up_sync(0xffffffffu, s, o);
    if (lane >= o) s += x;
  }
  if (lane == 31) ws[w] = s;
  __syncthreads();
  if (w == 0) {
    float x = (lane < 8) ? ws[lane] : 0.f;
#pragma unroll
    for (int o = 1; o < 8; o <<= 1) {
      float y = __shfl_up_sync(0xffffffffu, x, o);
      if (lane >= o) x += y;
    }
    if (lane < 8) ws[lane] = x;
  }
  __syncthreads();
  float off = s - v[7] + (w ? ws[w - 1] : 0.f);
#pragma unroll
  for (int j = 0; j < 8; j++) g_cum[n * S_ + t * 8 + j] = (v[j] + off) * L2E;
}

// ------------- fp16 GEMM, 128x128 tile, cp.async 2-stage, K-step 32 -------------
// MODE 0: x[4096,1024]@w[1024,3072] -> fp16 q/k/v planes (q scaled L2E/8)
// MODE 1: mix(planes)[4096,1024]@ow[1024,1024] -> fp32 d_out
template <int MODE>
__global__ __launch_bounds__(256) void gemm_kernel(float* __restrict__ outp) {
  constexpr int Nn = (MODE == 0) ? QKVN : H_;
  const __half* __restrict__ Ag = (MODE == 0) ? g_xf : g_mixf;
  const __half* __restrict__ Bg = (MODE == 0) ? g_wf : g_owf;

  __shared__ __align__(16) __half sA[2][128 * 40];   // 128 x 32 (pad 40)
  __shared__ __align__(16) __half sB[2][32 * 136];   // 32 x 128 (pad 136)

  const int tid = threadIdx.x, w = tid >> 5, lane = tid & 31;
  const int wm = w & 3, wn = w >> 2;
  const int row0 = blockIdx.y * 128, col0 = blockIdx.x * 128;

  float acc[2][8][4];
#pragma unroll
  for (int a = 0; a < 2; a++)
#pragma unroll
    for (int b = 0; b < 8; b++)
#pragma unroll
      for (int c = 0; c < 4; c++) acc[a][b][c] = 0.f;

  auto load_tile = [&](int st, int kt) {
#pragma unroll
    for (int p = 0; p < 2; p++) {  // A 128x32
      int i = tid + 256 * p;
      int r = i >> 2, seg = i & 3;
      int rg = row0 + r;
      long off;
      if (MODE == 0) {
        off = (long)rg * H_ + kt + seg * 8;
      } else {
        int k = kt + seg * 8;
        off = ((long)((rg >> 11) * N_ + (k >> 6)) * S_ + (rg & 2047)) * D_ + (k & 63);
      }
      cpa(sma(&sA[st][r * 40 + seg * 8]), &Ag[off]);
    }
#pragma unroll
    for (int p = 0; p < 2; p++) {  // B 32x128
      int i = tid + 256 * p;
      int r = i >> 4, c8 = i & 15;
      cpa(sma(&sB[st][r * 136 + c8 * 8]), &Bg[(long)(kt + r) * Nn + col0 + c8 * 8]);
    }
  };

  load_tile(0, 0);
  cpcommit();
  constexpr int NK = H_ / 32;
  for (int t = 0; t < NK; t++) {
    if (t + 1 < NK) load_tile((t + 1) & 1, (t + 1) * 32);
    cpcommit();
    cpwait<1>();
    __syncthreads();
    const int st = t & 1;
#pragma unroll
    for (int kc = 0; kc < 2; kc++) {
      uint32_t af[2][4];
#pragma unroll
      for (int mi = 0; mi < 2; mi++) {
        int r = wm * 32 + mi * 16 + (lane & 15);
        ldsm4(af[mi], sma(&sA[st][r * 40 + kc * 16 + (lane >> 4) * 8]));
      }
#pragma unroll
      for (int pr = 0; pr < 4; pr++) {
        uint32_t b4[4];
        int g = lane >> 3, r = lane & 7;
        int rb = kc * 16 + r + ((g & 1) ? 8 : 0);
        int cb = wn * 64 + pr * 16 + ((g >= 2) ? 8 : 0);
        ldsm4t(b4, sma(&sB[st][rb * 136 + cb]));
#pragma unroll
        for (int mi = 0; mi < 2; mi++) {
          mma_h(acc[mi][2 * pr], af[mi], b4[0], b4[1]);
          mma_h(acc[mi][2 * pr + 1], af[mi], b4[2], b4[3]);
        }
      }
    }
    __syncthreads();
  }
#pragma unroll
  for (int mi = 0; mi < 2; mi++)
#pragma unroll
    for (int nj = 0; nj < 8; nj++)
#pragma unroll
      for (int v = 0; v < 4; v++) {
        int rg = row0 + wm * 32 + mi * 16 + (lane >> 2) + ((v & 2) ? 8 : 0);
        int c = col0 + wn * 64 + nj * 8 + 2 * (lane & 3) + (v & 1);
        float val = acc[mi][nj][v];
        if (MODE == 0) {
          int m = c >> 10, nh = (c >> 6) & 15, d = c & 63;
          if (m == 0) val *= 0.125f * L2E;
          int b = rg >> 11, s = rg & 2047;
          long idx = ((long)(m * 32 + b * 16 + nh)) * PLANE + (long)s * D_ + d;
          g_qkvf[idx] = __float2half_rn(val);
        } else {
          outp[(long)rg * H_ + c] = val;
        }
      }
}

// ------------- causal flash attention, fp16 softmax pipe -------------
__global__ __launch_bounds__(256, 2) void flash_kernel() {
  const int qt = 15 - blockIdx.x;
  const int bh = blockIdx.y;
  const int n = bh & 15;
  const int q0 = qt * 128;
  const int tid = threadIdx.x, w = tid >> 5, lane = tid & 31;

  __shared__ __align__(16) __half fsm[18432];  // 36 KB: Q overlaps KV ring
  __shared__ float sBias[192];
  __half* sQ = fsm;
#define SK(st) (fsm + (st) * 9216)
#define SV(st) (fsm + (st) * 9216 + 4608)

  const long pl = (long)bh * PLANE;
  const __half* qg = g_qkvf + pl;
  const __half* kg = g_qkvf + MPLANE + pl;
  const __half* vg = g_qkvf + 2 * MPLANE + pl;

#pragma unroll
  for (int p = 0; p < 4; p++) {
    int i = tid + 256 * p;
    int r = i >> 3, c8 = i & 7;
    *(uint4*)&sQ[r * 72 + c8 * 8] = *(const uint4*)&qg[(long)(q0 + r) * D_ + c8 * 8];
  }
  __syncthreads();
  uint32_t qf[4][4];
  {
    int r = w * 16 + (lane & 15), cb = (lane >> 4) * 8;
#pragma unroll
    for (int kc = 0; kc < 4; kc++) ldsm4(qf[kc], sma(&sQ[r * 72 + kc * 16 + cb]));
  }
  __syncthreads();

  float Oa[8][4];
#pragma unroll
  for (int j = 0; j < 8; j++)
#pragma unroll
    for (int v = 0; v < 4; v++) Oa[j][v] = 0.f;
  float mrow[2] = {-1e30f, -1e30f}, lrow[2] = {0.f, 0.f};
  const float* cumn = g_cum + n * S_;
  const int ntiles = 2 * qt + 2;
  const int itop = q0 + w * 16 + 15;
  const int ibase = w * 16 + (lane >> 2) + 63 - 2 * (lane & 3);
  constexpr uint32_t ONE2 = 0x3C003C00u;  // half2(1,1)

  auto loadkv = [&](int st, int t) {
    int kv0 = t * 64;
#pragma unroll
    for (int p = 0; p < 2; p++) {
      int i = tid + 256 * p;
      int r = i >> 3, c8 = i & 7;
      long g = (long)(kv0 + r) * D_ + c8 * 8;
      cpa(sma(SK(st) + r * 72 + c8 * 8), kg + g);
      cpa(sma(SV(st) + r * 72 + c8 * 8), vg + g);
    }
  };

  loadkv(0, 0);
  cpcommit();
  for (int t = 0; t < ntiles; t++) {
    const int kv0 = t * 64;
    if (t + 1 < ntiles) loadkv((t + 1) & 1, t + 1);
    cpcommit();
    {  // stage bias window: sBias[i] = cum[q0-kv0-63+i]
      int base = q0 - kv0 - 63;
      if (tid < 192) {
        int src = base + tid;
        sBias[tid] = (src >= 0) ? cumn[src] : 0.f;
      }
    }
    cpwait<1>();
    __syncthreads();
    const int st = t & 1;
    if (kv0 <= itop) {
      float sc[8][4];
#pragma unroll
      for (int j = 0; j < 8; j++)
#pragma unroll
        for (int v = 0; v < 4; v++) sc[j][v] = 0.f;
#pragma unroll
      for (int kc = 0; kc < 4; kc++) {
#pragma unroll
        for (int pr = 0; pr < 4; pr++) {
          uint32_t b4[4];
          int g = lane >> 3, r = lane & 7;
          int rk = pr * 16 + r + ((g >= 2) ? 8 : 0);
          int ck = kc * 16 + ((g & 1) ? 8 : 0);
          ldsm4(b4, sma(SK(st) + rk * 72 + ck));
          mma_h(sc[2 * pr], qf[kc], b4[0], b4[1]);
          mma_h(sc[2 * pr + 1], qf[kc], b4[2], b4[3]);
        }
      }
      // bias + mask + max
      const bool full = (kv0 + 63 <= q0 + w * 16);
      const int dshift = q0 - kv0 - 63;
      float mx[2] = {-1e30f, -1e30f};
      if (full) {
#pragma unroll
        for (int j = 0; j < 8; j++)
#pragma unroll
          for (int v = 0; v < 4; v++) {
            int idx = ibase + ((v & 2) ? 8 : 0) - j * 8 - (v & 1);
            float s = sc[j][v] + sBias[idx];
            sc[j][v] = s;
            mx[v >> 1] = fmaxf(mx[v >> 1], s);
          }
      } else {
#pragma unroll
        for (int j = 0; j < 8; j++)
#pragma unroll
          for (int v = 0; v < 4; v++) {
            int idx = ibase + ((v & 2) ? 8 : 0) - j * 8 - (v & 1);
            float s = (dshift + idx < 0) ? -1e30f : sc[j][v] + sBias[idx];
            sc[j][v] = s;
            mx[v >> 1] = fmaxf(mx[v >> 1], s);
          }
      }
#pragma unroll
      for (int h = 0; h < 2; h++) {
        mx[h] = fmaxf(mx[h], __shfl_xor_sync(0xffffffffu, mx[h], 1));
        mx[h] = fmaxf(mx[h], __shfl_xor_sync(0xffffffffu, mx[h], 2));
      }
      float al[2];
#pragma unroll
      for (int h = 0; h < 2; h++) {
        float mn = fmaxf(mrow[h], mx[h]);
        al[h] = e2(mrow[h] - mn);
        mrow[h] = mn;
      }
      // P = 2^(s-m) on the fp16 pipe (packed A-fragments for PV)
      uint32_t ap[4][4];
#pragma unroll
      for (int kc = 0; kc < 4; kc++) {
        ap[kc][0] = h2ex2(pack2h(sc[2 * kc][0] - mrow[0], sc[2 * kc][1] - mrow[0]));
        ap[kc][1] = h2ex2(pack2h(sc[2 * kc][2] - mrow[1], sc[2 * kc][3] - mrow[1]));
        ap[kc][2] = h2ex2(pack2h(sc[2 * kc + 1][0] - mrow[0], sc[2 * kc + 1][1] - mrow[0]));
        ap[kc][3] = h2ex2(pack2h(sc[2 * kc + 1][2] - mrow[1], sc[2 * kc + 1][3] - mrow[1]));
      }
      // row sums via ones-MMA (fp32 accumulate; replicated across quad -> no shfl)
      float ps[4] = {0.f, 0.f, 0.f, 0.f};
#pragma unroll
      for (int kc = 0; kc < 4; kc++) mma_h(ps, ap[kc], ONE2, ONE2);
      lrow[0] = lrow[0] * al[0] + ps[0];
      lrow[1] = lrow[1] * al[1] + ps[2];
#pragma unroll
      for (int j = 0; j < 8; j++)
#pragma unroll
        for (int v = 0; v < 4; v++) Oa[j][v] *= al[v >> 1];
      // O += P V
#pragma unroll
      for (int kc = 0; kc < 4; kc++) {
#pragma unroll
        for (int pr = 0; pr < 4; pr++) {
          uint32_t b4[4];
          int g = lane >> 3, r = lane & 7;
          int rv = kc * 16 + r + ((g & 1) ? 8 : 0);
          int cv = pr * 16 + ((g >= 2) ? 8 : 0);
          ldsm4t(b4, sma(SV(st) + rv * 72 + cv));
          mma_h(Oa[2 * pr], ap[kc], b4[0], b4[1]);
          mma_h(Oa[2 * pr + 1], ap[kc], b4[2], b4[3]);
        }
      }
    }
    __syncthreads();
  }
  float inv[2] = {1.f / lrow[0], 1.f / lrow[1]};
  __half* mf = g_mixf + pl;
#pragma unroll
  for (int j = 0; j < 8; j++)
#pragma unroll
    for (int v = 0; v < 2; v++) {
      int ii = q0 + w * 16 + (lane >> 2) + v * 8;
      int d = j * 8 + 2 * (lane & 3);
      __half2 h = __floats2half2_rn(Oa[j][2 * v] * inv[v], Oa[j][2 * v + 1] * inv[v]);
      *(__half2*)&mf[(long)ii * D_ + d] = h;
    }
}

// ------------- launch -------------
extern "C" void kernel_launch(void* const* d_in, const int* in_sizes, int n_in,
                              void* d_out, int out_size) {
  const float* x = (const float*)d_in[0];
  const float* qkv = (const float*)d_in[1];
  const float* ow = (const float*)d_in[2];
  const float* rpe = (const float*)d_in[3];
  float* out = (float*)d_out;

  convert_all_kernel<<<(XN + WN + OWN) / 4 / 256, 256>>>(x, qkv, ow);
  cumsum_kernel<<<16, 256>>>(rpe);
  gemm_kernel<0><<<dim3(QKVN / 128, MROWS / 128), 256>>>(nullptr);
  flash_kernel<<<dim3(16, B_ * N_), 256>>>();
  gemm_kernel<1><<<dim3(H_ / 128, MROWS / 128), 256>>>(out);
}